// round 8
// baseline (speedup 1.0000x reference)
#include <cuda_runtime.h>
#include <cuda_bf16.h>
#include <math.h>
#include <stdint.h>

#define Bb 512
#define Ff 64
#define Tt 64
#define Hh 512
#define Kk 4
#define NN (3 * Hh)   // 1536

// ---------------- scratch (static device globals; no allocation) ----------------
__device__ __align__(16) float g_dataT[(size_t)Tt * Bb * Ff];            // [t][b][f]
__device__ __align__(16) __nv_bfloat16 g_xh[(size_t)Kk * Tt * Bb * Hh];  // x split hi
__device__ __align__(16) __nv_bfloat16 g_xl[(size_t)Kk * Tt * Bb * Hh];  // x split lo
__device__ __align__(16) __nv_bfloat16 g_Wih_h[(size_t)Kk * NN * Hh];
__device__ __align__(16) __nv_bfloat16 g_Wih_l[(size_t)Kk * NN * Hh];
__device__ __align__(16) __nv_bfloat16 g_Whh_h[(size_t)Kk * NN * Hh];
__device__ __align__(16) __nv_bfloat16 g_Whh_l[(size_t)Kk * NN * Hh];
// ping-pong hidden state (buffer = t&1 read, ^1 write) — avoids intra-launch WAR race
__device__ __align__(16) __nv_bfloat16 g_hh[2 * (size_t)Kk * Bb * Hh];
__device__ __align__(16) __nv_bfloat16 g_hl[2 * (size_t)Kk * Bb * Hh];
__device__ __align__(16) float g_h[2 * (size_t)Kk * Bb * Hh];
__device__ __align__(16) float g_gi[(size_t)Kk * Tt * Bb * NN];          // [k][(t,b)][comp 3H]
__device__ __align__(16) float g_hs[(size_t)Kk * Tt * Bb * Hh];          // [k][t][b][h]

// ---------------- helpers ----------------
__device__ __forceinline__ uint32_t smem_u32(const void* p) {
    uint32_t a;
    asm("{ .reg .u64 t; cvta.to.shared.u64 t, %1; cvt.u32.u64 %0, t; }" : "=r"(a) : "l"(p));
    return a;
}
__device__ __forceinline__ void cp16(uint32_t saddr, const void* g) {
    asm volatile("cp.async.cg.shared.global [%0], [%1], 16;" :: "r"(saddr), "l"(g));
}
__device__ __forceinline__ void cp_commit() {
    asm volatile("cp.async.commit_group;" ::: "memory");
}
template <int N> __device__ __forceinline__ void cp_wait() {
    asm volatile("cp.async.wait_group %0;" :: "n"(N) : "memory");
}
__device__ __forceinline__ void ldsm_x4(uint32_t a, uint32_t* r) {
    asm volatile("ldmatrix.sync.aligned.m8n8.x4.shared.b16 {%0,%1,%2,%3}, [%4];"
                 : "=r"(r[0]), "=r"(r[1]), "=r"(r[2]), "=r"(r[3]) : "r"(a));
}
__device__ __forceinline__ void mma16816(float* d, const uint32_t* a, const uint32_t* b) {
    asm volatile(
        "mma.sync.aligned.m16n8k16.row.col.f32.bf16.bf16.f32 "
        "{%0,%1,%2,%3}, {%4,%5,%6,%7}, {%8,%9}, {%0,%1,%2,%3};"
        : "+f"(d[0]), "+f"(d[1]), "+f"(d[2]), "+f"(d[3])
        : "r"(a[0]), "r"(a[1]), "r"(a[2]), "r"(a[3]), "r"(b[0]), "r"(b[1]));
}
__device__ __forceinline__ float sigm(float x) { return 1.f / (1.f + expf(-x)); }

// 32B rows (k-chunk 16 bf16), swizzle 16B chunk: c ^= (r>>2)&1
__device__ __forceinline__ uint32_t swz32(int r, int c) {
    return (uint32_t)(r * 32 + ((c ^ ((r >> 2) & 1)) << 4));
}
// composite col j = 24q + 8g + s  ->  original W row g*512 + 8q + s
__device__ __forceinline__ int c2o(int j) {
    return ((j >> 3) % 3) * Hh + (j / 24) * 8 + (j & 7);
}

// ---------------- data transpose: [B,F,T] -> [T,B,F] ----------------
__global__ void transpose_data(const float* __restrict__ data) {
    int idx = blockIdx.x * blockDim.x + threadIdx.x;
    if (idx >= Tt * Bb * Ff) return;
    int f = idx % Ff;
    int b = (idx / Ff) % Bb;
    int t = idx / (Ff * Bb);
    g_dataT[idx] = data[(size_t)b * Ff * Tt + (size_t)f * Tt + t];
}

// ---------------- input projection + ReLU -> x splits ----------------
__global__ void __launch_bounds__(256) proj_kernel(const float* __restrict__ fcW,
                                                   const float* __restrict__ fcB) {
    int kt = blockIdx.z;
    int k = kt >> 6;
    int t = kt & 63;
    int tt = (k < 2) ? t : (Tt - 1 - t);
    const float* A  = g_dataT + (size_t)tt * Bb * Ff;
    const float* Wk = fcW + (size_t)k * Hh * Ff;
    int b0 = blockIdx.x * 64, h0 = blockIdx.y * 64;

    __shared__ float As[Ff][64];
    __shared__ float Ws[Ff][64];
    int tid = threadIdx.x;

#pragma unroll
    for (int i = 0; i < 4; i++) {
        int li = tid + i * 256;
        int row = li >> 4;
        int fq = (li & 15) << 2;
        float4 v = *(const float4*)(A + (size_t)(b0 + row) * Ff + fq);
        As[fq + 0][row] = v.x; As[fq + 1][row] = v.y;
        As[fq + 2][row] = v.z; As[fq + 3][row] = v.w;
        float4 w = *(const float4*)(Wk + (size_t)(h0 + row) * Ff + fq);
        Ws[fq + 0][row] = w.x; Ws[fq + 1][row] = w.y;
        Ws[fq + 2][row] = w.z; Ws[fq + 3][row] = w.w;
    }
    __syncthreads();

    int ty = tid >> 4, tx = tid & 15;
    float acc[4][4] = {};
#pragma unroll 8
    for (int f = 0; f < Ff; f++) {
        float4 a = *(const float4*)&As[f][ty * 4];
        float4 w = *(const float4*)&Ws[f][tx * 4];
        float av[4] = {a.x, a.y, a.z, a.w};
        float wv[4] = {w.x, w.y, w.z, w.w};
#pragma unroll
        for (int i = 0; i < 4; i++)
#pragma unroll
            for (int j = 0; j < 4; j++) acc[i][j] += av[i] * wv[j];
    }

#pragma unroll
    for (int i = 0; i < 4; i++) {
        int b = b0 + ty * 4 + i;
        size_t rowoff = (((size_t)k * Tt + t) * Bb + b) * Hh;
#pragma unroll
        for (int j = 0; j < 4; j++) {
            int h = h0 + tx * 4 + j;
            float v = fmaxf(acc[i][j] + fcB[k * Hh + h], 0.f);
            __nv_bfloat16 hi = __float2bfloat16(v);
            g_xh[rowoff + h] = hi;
            g_xl[rowoff + h] = __float2bfloat16(v - __bfloat162float(hi));
        }
    }
}

// ---------------- weight splitting ----------------
__global__ void split_w(const float* __restrict__ Wih, const float* __restrict__ Whh) {
    const int NW = Kk * NN * Hh;
    int idx = blockIdx.x * 256 + threadIdx.x;
    if (idx < NW) {
        float v = Wih[idx];
        __nv_bfloat16 hi = __float2bfloat16(v);
        g_Wih_h[idx] = hi;
        g_Wih_l[idx] = __float2bfloat16(v - __bfloat162float(hi));
    } else {
        idx -= NW;
        float v = Whh[idx];
        __nv_bfloat16 hi = __float2bfloat16(v);
        g_Whh_h[idx] = hi;
        g_Whh_l[idx] = __float2bfloat16(v - __bfloat162float(hi));
    }
}

// ---------------- h init (+ split) -> buffer 0 ----------------
__global__ void init_h_kernel(const float* __restrict__ init) {
    int idx = blockIdx.x * 256 + threadIdx.x;   // K*B*H
    float v = init[idx % (Bb * Hh)];
    g_h[idx] = v;
    __nv_bfloat16 hi = __float2bfloat16(v);
    g_hh[idx] = hi;
    g_hl[idx] = __float2bfloat16(v - __bfloat162float(hi));
}

// ---------------- fused bf16x3 NT GEMM (composite-N) ----------------
// MODE 0 (gi): A = x splits (M = T*B), B = Wih comp, C = g_gi comp (+ bih)
// MODE 1 (step): A = h splits buf t&1 (M = B), epilogue = GRU gates -> buf (t&1)^1
// CTA tile: M=64, N=192 (8 octet-triples), K=512, k-chunk 16, 3-stage cp.async.
// 8 warps = 2(M) x 4(N): warp tile 32 x 48 (6 n8 tiles = 2 gate triples).
template <int MODE>
__global__ void __launch_bounds__(256, 2) gemm_fused(const float* __restrict__ bias, int t) {
    // stage = 16KB: A_hi[0,2K) A_lo[2K,4K) B_hi[4K,10K) B_lo[10K,16K); 3 stages
    __shared__ __align__(16) char smem[49152];
    uint32_t sb = smem_u32(smem);

    int tid = threadIdx.x, wid = tid >> 5, lane = tid & 31;
    int zz = blockIdx.z;
    int n0 = blockIdx.x * 192, m0 = blockIdx.y * 64;
    int warp_m = wid >> 2, warp_n = wid & 3;
    int rb = t & 1, wb = rb ^ 1;

    const __nv_bfloat16* Ah = (MODE == 0)
        ? g_xh + (size_t)zz * Tt * Bb * Hh
        : g_hh + ((size_t)rb * Kk + zz) * Bb * Hh;
    const __nv_bfloat16* Al = (MODE == 0)
        ? g_xl + (size_t)zz * Tt * Bb * Hh
        : g_hl + ((size_t)rb * Kk + zz) * Bb * Hh;
    const __nv_bfloat16* Bh = (MODE == 0 ? g_Wih_h : g_Whh_h) + (size_t)zz * NN * Hh;
    const __nv_bfloat16* Bl = (MODE == 0 ? g_Wih_l : g_Whh_l) + (size_t)zz * NN * Hh;

    float acc[2][6][4];
#pragma unroll
    for (int i = 0; i < 2; i++)
#pragma unroll
        for (int j = 0; j < 6; j++)
#pragma unroll
            for (int q = 0; q < 4; q++) acc[i][j][q] = 0.f;

    // 1024 16B chunks per stage / 256 threads = 4
    auto load_stage = [&](int s, int k0) {
        uint32_t st = sb + s * 16384;
        {   // A: idx 0..255
            int idx = tid;
            bool hi = idx < 128;
            int r = (idx & 127) >> 1, c = idx & 1;
            cp16(st + (hi ? 0 : 2048) + swz32(r, c),
                 (hi ? Ah : Al) + (size_t)(m0 + r) * Hh + k0 + c * 8);
        }
#pragma unroll
        for (int i = 1; i < 4; i++) {   // B: li 0..767
            int li = tid + (i - 1) * 256;
            bool hi = li < 384;
            int rr = (li % 384) >> 1, c = li & 1;
            int orig = c2o(n0 + rr);
            cp16(st + 4096 + (hi ? 0 : 6144) + swz32(rr, c),
                 (hi ? Bh : Bl) + (size_t)orig * Hh + k0 + c * 8);
        }
        cp_commit();
    };

    load_stage(0, 0);
    load_stage(1, 16);

    int cfr = lane >> 4;
    for (int kc = 0; kc < 32; kc++) {
        if (kc + 2 < 32) { load_stage((kc + 2) % 3, (kc + 2) * 16); cp_wait<2>(); }
        else if (kc + 1 < 32) cp_wait<1>();
        else cp_wait<0>();
        __syncthreads();

        uint32_t st = sb + (uint32_t)(kc % 3) * 16384;
        uint32_t a_h[2][4], a_l[2][4], b_h[6][2], b_l[6][2];
#pragma unroll
        for (int mi = 0; mi < 2; mi++) {
            int rA = warp_m * 32 + mi * 16 + (lane & 15);
            uint32_t ad = st + swz32(rA, cfr);
            ldsm_x4(ad, a_h[mi]);
            ldsm_x4(ad + 2048, a_l[mi]);
        }
#pragma unroll
        for (int nj = 0; nj < 3; nj++) {
            int rB = warp_n * 48 + nj * 16 + (lane & 15);
            uint32_t bd = st + 4096 + swz32(rB, cfr);
            uint32_t r4[4];
            ldsm_x4(bd, r4);
            b_h[2 * nj][0] = r4[0]; b_h[2 * nj][1] = r4[2];
            b_h[2 * nj + 1][0] = r4[1]; b_h[2 * nj + 1][1] = r4[3];
            ldsm_x4(bd + 6144, r4);
            b_l[2 * nj][0] = r4[0]; b_l[2 * nj][1] = r4[2];
            b_l[2 * nj + 1][0] = r4[1]; b_l[2 * nj + 1][1] = r4[3];
        }
#pragma unroll
        for (int mi = 0; mi < 2; mi++)
#pragma unroll
            for (int ni = 0; ni < 6; ni++) {
                mma16816(acc[mi][ni], a_h[mi], b_h[ni]);
                mma16816(acc[mi][ni], a_h[mi], b_l[ni]);
                mma16816(acc[mi][ni], a_l[mi], b_h[ni]);
            }
        __syncthreads();
    }

    int lane4 = lane >> 2;
    int cp2 = 2 * (lane & 3);

    if (MODE == 0) {
        // store acc + bih(comp) -> g_gi (rows m are t*B+b already)
        float* C = g_gi + (size_t)zz * Tt * Bb * NN;
        const float* bz = bias + (size_t)zz * NN;
#pragma unroll
        for (int nt = 0; nt < 6; nt++) {
            int j = n0 + warp_n * 48 + nt * 8 + cp2;
            int o = c2o(j);
            float b0 = bz[o], b1 = bz[o + 1];
#pragma unroll
            for (int mi = 0; mi < 2; mi++) {
                int row = m0 + warp_m * 32 + mi * 16 + lane4;
                float2 v0 = {acc[mi][nt][0] + b0, acc[mi][nt][1] + b1};
                float2 v1 = {acc[mi][nt][2] + b0, acc[mi][nt][3] + b1};
                *(float2*)(C + (size_t)row * NN + j) = v0;
                *(float2*)(C + (size_t)(row + 8) * NN + j) = v1;
            }
        }
    } else {
        // GRU gates in registers; read buf rb, write buf wb
        const float* giK = g_gi + (size_t)zz * Tt * Bb * NN;
        const float* bz = bias + (size_t)zz * NN;
#pragma unroll
        for (int tr = 0; tr < 2; tr++) {
            int jr = n0 + warp_n * 48 + tr * 24;    // composite col of r-group
            int h0e = (jr / 24) * 8 + cp2;          // h index for this col pair
            float br0 = bz[h0e],        br1 = bz[h0e + 1];
            float bz0 = bz[Hh + h0e],   bz1 = bz[Hh + h0e + 1];
            float bn0 = bz[2 * Hh + h0e], bn1 = bz[2 * Hh + h0e + 1];
#pragma unroll
            for (int mi = 0; mi < 2; mi++)
#pragma unroll
                for (int v = 0; v < 2; v++) {
                    int b = m0 + warp_m * 32 + mi * 16 + lane4 + 8 * v;
                    const float* gi = giK + ((size_t)t * Bb + b) * NN + jr + cp2;
                    float2 gir = *(const float2*)(gi);
                    float2 giz = *(const float2*)(gi + 8);
                    float2 gin = *(const float2*)(gi + 16);
                    float2 hp = *(const float2*)(
                        g_h + (((size_t)rb * Kk + zz) * Bb + b) * Hh + h0e);
                    int q = 2 * v;
                    float R0 = sigm(gir.x + acc[mi][3 * tr + 0][q] + br0);
                    float Z0 = sigm(giz.x + acc[mi][3 * tr + 1][q] + bz0);
                    float N0 = tanhf(gin.x + R0 * (acc[mi][3 * tr + 2][q] + bn0));
                    float hn0 = (1.f - Z0) * N0 + Z0 * hp.x;
                    float R1 = sigm(gir.y + acc[mi][3 * tr + 0][q + 1] + br1);
                    float Z1 = sigm(giz.y + acc[mi][3 * tr + 1][q + 1] + bz1);
                    float N1 = tanhf(gin.y + R1 * (acc[mi][3 * tr + 2][q + 1] + bn1));
                    float hn1 = (1.f - Z1) * N1 + Z1 * hp.y;

                    size_t hoff = (((size_t)wb * Kk + zz) * Bb + b) * Hh + h0e;
                    *(float2*)(g_h + hoff) = make_float2(hn0, hn1);
                    *(float2*)(g_hs + (((size_t)zz * Tt + t) * Bb + b) * Hh + h0e) =
                        make_float2(hn0, hn1);
                    __nv_bfloat162 hv, lv;
                    hv.x = __float2bfloat16(hn0);
                    hv.y = __float2bfloat16(hn1);
                    lv.x = __float2bfloat16(hn0 - __bfloat162float(hv.x));
                    lv.y = __float2bfloat16(hn1 - __bfloat162float(hv.y));
                    *(__nv_bfloat162*)(g_hh + hoff) = hv;
                    *(__nv_bfloat162*)(g_hl + hoff) = lv;
                }
        }
    }
}

// ---------------- output heads ----------------
__global__ void out_kernel(const float* __restrict__ Wout,
                           const float* __restrict__ bout,
                           float* __restrict__ out) {
    int warp = threadIdx.x >> 5;
    int lane = threadIdx.x & 31;
    int oid = blockIdx.x * 8 + warp;
    int pair = oid >> 15;
    int rem = oid & 32767;
    int b = rem >> 6;
    int t = rem & 63;
    const float* hf = g_hs + (((size_t)pair * Tt + t) * Bb + b) * Hh;
    const float* hb = g_hs + (((size_t)(pair + 2) * Tt + (Tt - 1 - t)) * Bb + b) * Hh;
    const float* w = Wout + pair * Hh;
    float s = 0.f;
    for (int i0 = lane * 4; i0 < Hh; i0 += 128) {
        float4 f = *(const float4*)(hf + i0);
        float4 g = *(const float4*)(hb + i0);
        float4 wv = *(const float4*)(w + i0);
        s += (f.x + g.x) * wv.x + (f.y + g.y) * wv.y +
             (f.z + g.z) * wv.z + (f.w + g.w) * wv.w;
    }
#pragma unroll
    for (int o = 16; o; o >>= 1) s += __shfl_xor_sync(0xffffffffu, s, o);
    if (lane == 0) out[(size_t)pair * Bb * Tt + b * Tt + t] = s + bout[pair];
}

// ---------------- launch (kernel launches ONLY) ----------------
extern "C" void kernel_launch(void* const* d_in, const int* in_sizes, int n_in,
                              void* d_out, int out_size) {
    const float* data     = (const float*)d_in[0];
    const float* init     = (const float*)d_in[1];
    const float* fc_in_W  = (const float*)d_in[2];
    const float* fc_in_b  = (const float*)d_in[3];
    const float* Wih      = (const float*)d_in[4];
    const float* Whh      = (const float*)d_in[5];
    const float* bih      = (const float*)d_in[6];
    const float* bhh      = (const float*)d_in[7];
    const float* fc_out_W = (const float*)d_in[8];
    const float* fc_out_b = (const float*)d_in[9];
    float* out = (float*)d_out;

    transpose_data<<<(Tt * Bb * Ff) / 256, 256>>>(data);
    proj_kernel<<<dim3(Bb / 64, Hh / 64, Kk * Tt), 256>>>(fc_in_W, fc_in_b);
    split_w<<<(2 * Kk * NN * Hh) / 256, 256>>>(Wih, Whh);

    // gi (composite cols): M = T*B = 32768 -> grid (8, 512, 4)
    gemm_fused<0><<<dim3(NN / 192, (Tt * Bb) / 64, Kk), 256>>>(bih, 0);

    init_h_kernel<<<(Kk * Bb * Hh) / 256, 256>>>(init);

    for (int t = 0; t < Tt; t++) {
        // fused gh GEMM + GRU gates: grid (8, 8, 4) = 256 CTAs
        gemm_fused<1><<<dim3(NN / 192, Bb / 64, Kk), 256>>>(bhh, t);
    }

    out_kernel<<<(2 * Bb * Tt) / 8, 256>>>(fc_out_W, fc_out_b, out);
}

// round 9
// speedup vs baseline: 1.0187x; 1.0187x over previous
#include <cuda_runtime.h>
#include <cuda_bf16.h>
#include <math.h>
#include <stdint.h>

#define Bb 512
#define Ff 64
#define Tt 64
#define Hh 512
#define Kk 4
#define NN (3 * Hh)   // 1536

// ---------------- scratch (static device globals; no allocation) ----------------
__device__ __align__(16) __nv_bfloat16 g_dh[(size_t)Tt * Bb * Ff];       // data splits [t][b][f]
__device__ __align__(16) __nv_bfloat16 g_dl[(size_t)Tt * Bb * Ff];
__device__ __align__(16) __nv_bfloat16 g_fcW_h[(size_t)Kk * Hh * Ff];
__device__ __align__(16) __nv_bfloat16 g_fcW_l[(size_t)Kk * Hh * Ff];
__device__ __align__(16) __nv_bfloat16 g_xh[(size_t)Kk * Tt * Bb * Hh];  // x split hi
__device__ __align__(16) __nv_bfloat16 g_xl[(size_t)Kk * Tt * Bb * Hh];  // x split lo
__device__ __align__(16) __nv_bfloat16 g_Wih_h[(size_t)Kk * NN * Hh];
__device__ __align__(16) __nv_bfloat16 g_Wih_l[(size_t)Kk * NN * Hh];
__device__ __align__(16) __nv_bfloat16 g_Whh_h[(size_t)Kk * NN * Hh];
__device__ __align__(16) __nv_bfloat16 g_Whh_l[(size_t)Kk * NN * Hh];
// ping-pong hidden state (buffer = t&1 read, ^1 write) — avoids intra-launch WAR race
__device__ __align__(16) __nv_bfloat16 g_hh[2 * (size_t)Kk * Bb * Hh];
__device__ __align__(16) __nv_bfloat16 g_hl[2 * (size_t)Kk * Bb * Hh];
__device__ __align__(16) float g_h[2 * (size_t)Kk * Bb * Hh];
__device__ __align__(16) float g_gi[(size_t)Kk * Tt * Bb * NN];          // [k][(t,b)][comp 3H]
__device__ __align__(16) float g_hs[(size_t)Kk * Tt * Bb * Hh];          // [k][t][b][h]

// ---------------- helpers ----------------
__device__ __forceinline__ uint32_t smem_u32(const void* p) {
    uint32_t a;
    asm("{ .reg .u64 t; cvta.to.shared.u64 t, %1; cvt.u32.u64 %0, t; }" : "=r"(a) : "l"(p));
    return a;
}
__device__ __forceinline__ void cp16(uint32_t saddr, const void* g) {
    asm volatile("cp.async.cg.shared.global [%0], [%1], 16;" :: "r"(saddr), "l"(g));
}
__device__ __forceinline__ void cp_commit() {
    asm volatile("cp.async.commit_group;" ::: "memory");
}
template <int N> __device__ __forceinline__ void cp_wait() {
    asm volatile("cp.async.wait_group %0;" :: "n"(N) : "memory");
}
__device__ __forceinline__ void ldsm_x4(uint32_t a, uint32_t* r) {
    asm volatile("ldmatrix.sync.aligned.m8n8.x4.shared.b16 {%0,%1,%2,%3}, [%4];"
                 : "=r"(r[0]), "=r"(r[1]), "=r"(r[2]), "=r"(r[3]) : "r"(a));
}
__device__ __forceinline__ void mma16816(float* d, const uint32_t* a, const uint32_t* b) {
    asm volatile(
        "mma.sync.aligned.m16n8k16.row.col.f32.bf16.bf16.f32 "
        "{%0,%1,%2,%3}, {%4,%5,%6,%7}, {%8,%9}, {%0,%1,%2,%3};"
        : "+f"(d[0]), "+f"(d[1]), "+f"(d[2]), "+f"(d[3])
        : "r"(a[0]), "r"(a[1]), "r"(a[2]), "r"(a[3]), "r"(b[0]), "r"(b[1]));
}
__device__ __forceinline__ float sigm(float x) { return 1.f / (1.f + expf(-x)); }

// 32B rows (k-chunk 16 bf16), swizzle 16B chunk: c ^= (r>>2)&1
__device__ __forceinline__ uint32_t swz32(int r, int c) {
    return (uint32_t)(r * 32 + ((c ^ ((r >> 2) & 1)) << 4));
}
// composite col j = 24q + 8g + s  ->  original W row g*512 + 8q + s
__device__ __forceinline__ int c2o(int j) {
    return ((j >> 3) % 3) * Hh + (j / 24) * 8 + (j & 7);
}

// ---------------- data transpose + split: [B,F,T] -> bf16 hi/lo [T,B,F] ----------------
__global__ void transpose_data(const float* __restrict__ data) {
    int idx = blockIdx.x * blockDim.x + threadIdx.x;
    if (idx >= Tt * Bb * Ff) return;
    int f = idx % Ff;
    int b = (idx / Ff) % Bb;
    int t = idx / (Ff * Bb);
    float v = data[(size_t)b * Ff * Tt + (size_t)f * Tt + t];
    __nv_bfloat16 hi = __float2bfloat16(v);
    g_dh[idx] = hi;
    g_dl[idx] = __float2bfloat16(v - __bfloat162float(hi));
}

// ---------------- weight splitting (Wih, Whh, fc_in_W) ----------------
__global__ void split_w3(const float* __restrict__ Wih, const float* __restrict__ Whh,
                         const float* __restrict__ fcW) {
    const int NW = Kk * NN * Hh;
    const int NF = Kk * Hh * Ff;
    int idx = blockIdx.x * 256 + threadIdx.x;
    if (idx < NW) {
        float v = Wih[idx];
        __nv_bfloat16 hi = __float2bfloat16(v);
        g_Wih_h[idx] = hi;
        g_Wih_l[idx] = __float2bfloat16(v - __bfloat162float(hi));
    } else if (idx < 2 * NW) {
        int i = idx - NW;
        float v = Whh[i];
        __nv_bfloat16 hi = __float2bfloat16(v);
        g_Whh_h[i] = hi;
        g_Whh_l[i] = __float2bfloat16(v - __bfloat162float(hi));
    } else if (idx < 2 * NW + NF) {
        int i = idx - 2 * NW;
        float v = fcW[i];
        __nv_bfloat16 hi = __float2bfloat16(v);
        g_fcW_h[i] = hi;
        g_fcW_l[i] = __float2bfloat16(v - __bfloat162float(hi));
    }
}

// ---------------- h init (+ split) -> buffer 0 ----------------
__global__ void init_h_kernel(const float* __restrict__ init) {
    int idx = blockIdx.x * 256 + threadIdx.x;   // K*B*H
    float v = init[idx % (Bb * Hh)];
    g_h[idx] = v;
    __nv_bfloat16 hi = __float2bfloat16(v);
    g_hh[idx] = hi;
    g_hl[idx] = __float2bfloat16(v - __bfloat162float(hi));
}

// ---------------- proj: bf16x3 HMMA, M128 x N128, K=64 -> relu + split ----------------
// A rows = data[tt][b][f] (tt reversed for cells 2,3); B rows = fc_in_W[k][h][f].
__global__ void __launch_bounds__(256, 1) proj_hmma(const float* __restrict__ fcB) {
    // stage 16KB: A_hi[0,4K) A_lo[4K,8K) B_hi[8K,12K) B_lo[12K,16K); 2 stages
    __shared__ __align__(16) char smem[32768];
    uint32_t sb = smem_u32(smem);
    int tid = threadIdx.x, wid = tid >> 5, lane = tid & 31;
    int z = blockIdx.z;
    int n0 = blockIdx.x * 128, m0 = blockIdx.y * 128;
    int warp_m = wid >> 2, warp_n = wid & 3;      // warp tile 64 x 32
    int t = m0 >> 9, b0 = m0 & 511;
    int tt = (z < 2) ? t : (Tt - 1 - t);

    const __nv_bfloat16* Ah = g_dh + ((size_t)tt * Bb + b0) * Ff;
    const __nv_bfloat16* Al = g_dl + ((size_t)tt * Bb + b0) * Ff;
    const __nv_bfloat16* Bh = g_fcW_h + (size_t)z * Hh * Ff;
    const __nv_bfloat16* Bl = g_fcW_l + (size_t)z * Hh * Ff;

    float acc[4][4][4];
#pragma unroll
    for (int i = 0; i < 4; i++)
#pragma unroll
        for (int j = 0; j < 4; j++)
#pragma unroll
            for (int q = 0; q < 4; q++) acc[i][j][q] = 0.f;

    auto load_stage = [&](int s, int k0) {
        uint32_t st = sb + s * 16384;
#pragma unroll
        for (int i = 0; i < 4; i++) {
            int idx = tid + i * 256;           // 0..1023
            if (idx < 512) {                   // A hi/lo, 256 chunks each
                bool hi = idx < 256;
                int li = idx & 255;
                int r = li >> 1, c = li & 1;
                cp16(st + (hi ? 0 : 4096) + swz32(r, c),
                     (hi ? Ah : Al) + (size_t)r * Ff + k0 + c * 8);
            } else {                           // B hi/lo
                int li = idx - 512;
                bool hi = li < 256;
                li &= 255;
                int r = li >> 1, c = li & 1;
                cp16(st + 8192 + (hi ? 0 : 4096) + swz32(r, c),
                     (hi ? Bh : Bl) + (size_t)(n0 + r) * Ff + k0 + c * 8);
            }
        }
        cp_commit();
    };

    load_stage(0, 0);
    int cfr = lane >> 4;
    for (int kc = 0; kc < 4; kc++) {
        if (kc + 1 < 4) { load_stage((kc + 1) & 1, (kc + 1) * 16); cp_wait<1>(); }
        else cp_wait<0>();
        __syncthreads();
        uint32_t st = sb + (uint32_t)(kc & 1) * 16384;
        uint32_t a_h[4][4], a_l[4][4], b_h[4][2], b_l[4][2];
#pragma unroll
        for (int mi = 0; mi < 4; mi++) {
            int rA = warp_m * 64 + mi * 16 + (lane & 15);
            uint32_t ad = st + swz32(rA, cfr);
            ldsm_x4(ad, a_h[mi]);
            ldsm_x4(ad + 4096, a_l[mi]);
        }
#pragma unroll
        for (int nj = 0; nj < 2; nj++) {
            int rB = warp_n * 32 + nj * 16 + (lane & 15);
            uint32_t bd = st + 8192 + swz32(rB, cfr);
            uint32_t r4[4];
            ldsm_x4(bd, r4);
            b_h[2 * nj][0] = r4[0]; b_h[2 * nj][1] = r4[2];
            b_h[2 * nj + 1][0] = r4[1]; b_h[2 * nj + 1][1] = r4[3];
            ldsm_x4(bd + 4096, r4);
            b_l[2 * nj][0] = r4[0]; b_l[2 * nj][1] = r4[2];
            b_l[2 * nj + 1][0] = r4[1]; b_l[2 * nj + 1][1] = r4[3];
        }
#pragma unroll
        for (int mi = 0; mi < 4; mi++)
#pragma unroll
            for (int ni = 0; ni < 4; ni++) {
                mma16816(acc[mi][ni], a_h[mi], b_h[ni]);
                mma16816(acc[mi][ni], a_h[mi], b_l[ni]);
                mma16816(acc[mi][ni], a_l[mi], b_h[ni]);
            }
        __syncthreads();
    }

    int lane4 = lane >> 2;
    int cp2 = 2 * (lane & 3);
    const float* bz = fcB + (size_t)z * Hh;
#pragma unroll
    for (int mi = 0; mi < 4; mi++)
#pragma unroll
        for (int v = 0; v < 2; v++) {
            int rl = warp_m * 64 + mi * 16 + lane4 + 8 * v;
            size_t rowoff = (((size_t)z * Tt + t) * Bb + (b0 + rl)) * Hh;
#pragma unroll
            for (int ni = 0; ni < 4; ni++) {
                int h = n0 + warp_n * 32 + ni * 8 + cp2;
                int q = 2 * v;
                float v0 = fmaxf(acc[mi][ni][q] + bz[h], 0.f);
                float v1 = fmaxf(acc[mi][ni][q + 1] + bz[h + 1], 0.f);
                __nv_bfloat162 hv, lv;
                hv.x = __float2bfloat16(v0);
                hv.y = __float2bfloat16(v1);
                lv.x = __float2bfloat16(v0 - __bfloat162float(hv.x));
                lv.y = __float2bfloat16(v1 - __bfloat162float(hv.y));
                *(__nv_bfloat162*)(g_xh + rowoff + h) = hv;
                *(__nv_bfloat162*)(g_xl + rowoff + h) = lv;
            }
        }
}

// ---------------- fused bf16x3 NT GEMM (composite-N), M128 x N192, warp 64x48 ----------
// MODE 0 (gi): A = x splits (M = T*B), C = g_gi comp (+ bih)
// MODE 1 (step): A = h splits buf t&1 (M = B), epilogue = GRU gates -> buf (t&1)^1
template <int MODE>
__global__ void __launch_bounds__(256, 1) gemm_fused(const float* __restrict__ bias, int t) {
    // stage 20KB: A_hi[0,4K) A_lo[4K,8K) B_hi[8K,14K) B_lo[14K,20K); 2 stages
    __shared__ __align__(16) char smem[40960];
    uint32_t sb = smem_u32(smem);

    int tid = threadIdx.x, wid = tid >> 5, lane = tid & 31;
    int zz = blockIdx.z;
    int n0 = blockIdx.x * 192, m0 = blockIdx.y * 128;
    int warp_m = wid >> 2, warp_n = wid & 3;      // warp tile 64 x 48
    int rb = t & 1, wb = rb ^ 1;

    const __nv_bfloat16* Ah = (MODE == 0)
        ? g_xh + (size_t)zz * Tt * Bb * Hh
        : g_hh + ((size_t)rb * Kk + zz) * Bb * Hh;
    const __nv_bfloat16* Al = (MODE == 0)
        ? g_xl + (size_t)zz * Tt * Bb * Hh
        : g_hl + ((size_t)rb * Kk + zz) * Bb * Hh;
    const __nv_bfloat16* Bh = (MODE == 0 ? g_Wih_h : g_Whh_h) + (size_t)zz * NN * Hh;
    const __nv_bfloat16* Bl = (MODE == 0 ? g_Wih_l : g_Whh_l) + (size_t)zz * NN * Hh;

    float acc[4][6][4];
#pragma unroll
    for (int i = 0; i < 4; i++)
#pragma unroll
        for (int j = 0; j < 6; j++)
#pragma unroll
            for (int q = 0; q < 4; q++) acc[i][j][q] = 0.f;

    // 1280 16B chunks per stage / 256 threads = 5
    auto load_stage = [&](int s, int k0) {
        uint32_t st = sb + s * 20480;
#pragma unroll
        for (int i = 0; i < 2; i++) {          // A: 512 chunks
            int idx = tid + i * 256;
            bool hi = idx < 256;
            int li = idx & 255;
            int r = li >> 1, c = li & 1;
            cp16(st + (hi ? 0 : 4096) + swz32(r, c),
                 (hi ? Ah : Al) + (size_t)(m0 + r) * Hh + k0 + c * 8);
        }
#pragma unroll
        for (int i = 2; i < 5; i++) {          // B: 768 chunks
            int li = tid + (i - 2) * 256;
            bool hi = li < 384;
            int lj = li % 384;
            int rr = lj >> 1, c = lj & 1;
            cp16(st + 8192 + (hi ? 0 : 6144) + swz32(rr, c),
                 (hi ? Bh : Bl) + (size_t)c2o(n0 + rr) * Hh + k0 + c * 8);
        }
        cp_commit();
    };

    load_stage(0, 0);
    int cfr = lane >> 4;
    for (int kc = 0; kc < 32; kc++) {
        if (kc + 1 < 32) { load_stage((kc + 1) & 1, (kc + 1) * 16); cp_wait<1>(); }
        else cp_wait<0>();
        __syncthreads();

        uint32_t st = sb + (uint32_t)(kc & 1) * 20480;
        uint32_t a_h[4][4], a_l[4][4], b_h[6][2], b_l[6][2];
#pragma unroll
        for (int mi = 0; mi < 4; mi++) {
            int rA = warp_m * 64 + mi * 16 + (lane & 15);
            uint32_t ad = st + swz32(rA, cfr);
            ldsm_x4(ad, a_h[mi]);
            ldsm_x4(ad + 4096, a_l[mi]);
        }
#pragma unroll
        for (int nj = 0; nj < 3; nj++) {
            int rB = warp_n * 48 + nj * 16 + (lane & 15);
            uint32_t bd = st + 8192 + swz32(rB, cfr);
            uint32_t r4[4];
            ldsm_x4(bd, r4);
            b_h[2 * nj][0] = r4[0]; b_h[2 * nj][1] = r4[2];
            b_h[2 * nj + 1][0] = r4[1]; b_h[2 * nj + 1][1] = r4[3];
            ldsm_x4(bd + 6144, r4);
            b_l[2 * nj][0] = r4[0]; b_l[2 * nj][1] = r4[2];
            b_l[2 * nj + 1][0] = r4[1]; b_l[2 * nj + 1][1] = r4[3];
        }
#pragma unroll
        for (int mi = 0; mi < 4; mi++)
#pragma unroll
            for (int ni = 0; ni < 6; ni++) {
                mma16816(acc[mi][ni], a_h[mi], b_h[ni]);
                mma16816(acc[mi][ni], a_h[mi], b_l[ni]);
                mma16816(acc[mi][ni], a_l[mi], b_h[ni]);
            }
        __syncthreads();
    }

    int lane4 = lane >> 2;
    int cp2 = 2 * (lane & 3);

    if (MODE == 0) {
        float* C = g_gi + (size_t)zz * Tt * Bb * NN;
        const float* bz = bias + (size_t)zz * NN;
#pragma unroll
        for (int nt = 0; nt < 6; nt++) {
            int j = n0 + warp_n * 48 + nt * 8 + cp2;
            int o = c2o(j);
            float b0 = bz[o], b1 = bz[o + 1];
#pragma unroll
            for (int mi = 0; mi < 4; mi++) {
                int row = m0 + warp_m * 64 + mi * 16 + lane4;
                float2 v0 = {acc[mi][nt][0] + b0, acc[mi][nt][1] + b1};
                float2 v1 = {acc[mi][nt][2] + b0, acc[mi][nt][3] + b1};
                *(float2*)(C + (size_t)row * NN + j) = v0;
                *(float2*)(C + (size_t)(row + 8) * NN + j) = v1;
            }
        }
    } else {
        // GRU gates in registers; read buf rb, write buf wb
        const float* giK = g_gi + (size_t)zz * Tt * Bb * NN;
        const float* bz = bias + (size_t)zz * NN;
#pragma unroll
        for (int tr = 0; tr < 2; tr++) {
            int jr = n0 + warp_n * 48 + tr * 24;    // composite col of r-group
            int h0e = (jr / 24) * 8 + cp2;          // h index for this col pair
            float br0 = bz[h0e],        br1 = bz[h0e + 1];
            float bz0 = bz[Hh + h0e],   bz1 = bz[Hh + h0e + 1];
            float bn0 = bz[2 * Hh + h0e], bn1 = bz[2 * Hh + h0e + 1];
#pragma unroll
            for (int mi = 0; mi < 4; mi++)
#pragma unroll
                for (int v = 0; v < 2; v++) {
                    int b = m0 + warp_m * 64 + mi * 16 + lane4 + 8 * v;
                    const float* gi = giK + ((size_t)t * Bb + b) * NN + jr + cp2;
                    float2 gir = *(const float2*)(gi);
                    float2 giz = *(const float2*)(gi + 8);
                    float2 gin = *(const float2*)(gi + 16);
                    float2 hp = *(const float2*)(
                        g_h + (((size_t)rb * Kk + zz) * Bb + b) * Hh + h0e);
                    int q = 2 * v;
                    float R0 = sigm(gir.x + acc[mi][3 * tr + 0][q] + br0);
                    float Z0 = sigm(giz.x + acc[mi][3 * tr + 1][q] + bz0);
                    float N0 = tanhf(gin.x + R0 * (acc[mi][3 * tr + 2][q] + bn0));
                    float hn0 = (1.f - Z0) * N0 + Z0 * hp.x;
                    float R1 = sigm(gir.y + acc[mi][3 * tr + 0][q + 1] + br1);
                    float Z1 = sigm(giz.y + acc[mi][3 * tr + 1][q + 1] + bz1);
                    float N1 = tanhf(gin.y + R1 * (acc[mi][3 * tr + 2][q + 1] + bn1));
                    float hn1 = (1.f - Z1) * N1 + Z1 * hp.y;

                    size_t hoff = (((size_t)wb * Kk + zz) * Bb + b) * Hh + h0e;
                    *(float2*)(g_h + hoff) = make_float2(hn0, hn1);
                    *(float2*)(g_hs + (((size_t)zz * Tt + t) * Bb + b) * Hh + h0e) =
                        make_float2(hn0, hn1);
                    __nv_bfloat162 hv, lv;
                    hv.x = __float2bfloat16(hn0);
                    hv.y = __float2bfloat16(hn1);
                    lv.x = __float2bfloat16(hn0 - __bfloat162float(hv.x));
                    lv.y = __float2bfloat16(hn1 - __bfloat162float(hv.y));
                    *(__nv_bfloat162*)(g_hh + hoff) = hv;
                    *(__nv_bfloat162*)(g_hl + hoff) = lv;
                }
        }
    }
}

// ---------------- output heads ----------------
__global__ void out_kernel(const float* __restrict__ Wout,
                           const float* __restrict__ bout,
                           float* __restrict__ out) {
    int warp = threadIdx.x >> 5;
    int lane = threadIdx.x & 31;
    int oid = blockIdx.x * 8 + warp;
    int pair = oid >> 15;
    int rem = oid & 32767;
    int b = rem >> 6;
    int t = rem & 63;
    const float* hf = g_hs + (((size_t)pair * Tt + t) * Bb + b) * Hh;
    const float* hb = g_hs + (((size_t)(pair + 2) * Tt + (Tt - 1 - t)) * Bb + b) * Hh;
    const float* w = Wout + pair * Hh;
    float s = 0.f;
    for (int i0 = lane * 4; i0 < Hh; i0 += 128) {
        float4 f = *(const float4*)(hf + i0);
        float4 g = *(const float4*)(hb + i0);
        float4 wv = *(const float4*)(w + i0);
        s += (f.x + g.x) * wv.x + (f.y + g.y) * wv.y +
             (f.z + g.z) * wv.z + (f.w + g.w) * wv.w;
    }
#pragma unroll
    for (int o = 16; o; o >>= 1) s += __shfl_xor_sync(0xffffffffu, s, o);
    if (lane == 0) out[(size_t)pair * Bb * Tt + b * Tt + t] = s + bout[pair];
}

// ---------------- launch (kernel launches ONLY) ----------------
extern "C" void kernel_launch(void* const* d_in, const int* in_sizes, int n_in,
                              void* d_out, int out_size) {
    const float* data     = (const float*)d_in[0];
    const float* init     = (const float*)d_in[1];
    const float* fc_in_W  = (const float*)d_in[2];
    const float* fc_in_b  = (const float*)d_in[3];
    const float* Wih      = (const float*)d_in[4];
    const float* Whh      = (const float*)d_in[5];
    const float* bih      = (const float*)d_in[6];
    const float* bhh      = (const float*)d_in[7];
    const float* fc_out_W = (const float*)d_in[8];
    const float* fc_out_b = (const float*)d_in[9];
    float* out = (float*)d_out;

    transpose_data<<<(Tt * Bb * Ff) / 256, 256>>>(data);
    split_w3<<<(2 * Kk * NN * Hh + Kk * Hh * Ff) / 256, 256>>>(Wih, Whh, fc_in_W);

    // proj (HMMA): M = T*B per cell, N = 512, K = 64
    proj_hmma<<<dim3(Hh / 128, (Tt * Bb) / 128, Kk), 256>>>(fc_in_b);

    // gi (composite cols): M = T*B = 32768 -> grid (8, 256, 4)
    gemm_fused<0><<<dim3(NN / 192, (Tt * Bb) / 128, Kk), 256>>>(bih, 0);

    init_h_kernel<<<(Kk * Bb * Hh) / 256, 256>>>(init);

    for (int t = 0; t < Tt; t++) {
        // fused gh GEMM + GRU gates: grid (8, 4, 4) = 128 CTAs
        gemm_fused<1><<<dim3(NN / 192, Bb / 128, Kk), 256>>>(bhh, t);
    }

    out_kernel<<<(2 * Bb * Tt) / 8, 256>>>(fc_out_W, fc_out_b, out);
}

// round 10
// speedup vs baseline: 1.1989x; 1.1769x over previous
#include <cuda_runtime.h>
#include <cuda_bf16.h>
#include <math.h>
#include <stdint.h>

#define Bb 512
#define Ff 64
#define Tt 64
#define Hh 512
#define Kk 4
#define NN (3 * Hh)   // 1536

// ---------------- scratch (static device globals; no allocation) ----------------
__device__ __align__(16) __nv_bfloat16 g_dh[(size_t)Tt * Bb * Ff];       // data splits [t][b][f]
__device__ __align__(16) __nv_bfloat16 g_dl[(size_t)Tt * Bb * Ff];
__device__ __align__(16) __nv_bfloat16 g_fcW_h[(size_t)Kk * Hh * Ff];
__device__ __align__(16) __nv_bfloat16 g_fcW_l[(size_t)Kk * Hh * Ff];
__device__ __align__(16) __nv_bfloat16 g_xh[(size_t)Kk * Tt * Bb * Hh];  // x split hi
__device__ __align__(16) __nv_bfloat16 g_xl[(size_t)Kk * Tt * Bb * Hh];  // x split lo
__device__ __align__(16) __nv_bfloat16 g_Wih_h[(size_t)Kk * NN * Hh];
__device__ __align__(16) __nv_bfloat16 g_Wih_l[(size_t)Kk * NN * Hh];
__device__ __align__(16) __nv_bfloat16 g_Whh_h[(size_t)Kk * NN * Hh];
__device__ __align__(16) __nv_bfloat16 g_Whh_l[(size_t)Kk * NN * Hh];
__device__ __align__(16) __nv_bfloat16 g_hh[(size_t)Kk * Bb * Hh];
__device__ __align__(16) __nv_bfloat16 g_hl[(size_t)Kk * Bb * Hh];
__device__ __align__(16) float g_gi[(size_t)Kk * Tt * Bb * NN];          // [k][(t,b)][3H]
__device__ __align__(16) float g_gh[(size_t)Kk * Bb * NN];               // [k][b][3H]
__device__ __align__(16) float g_h[(size_t)Kk * Bb * Hh];                // [k][b][h]
__device__ __align__(16) float g_hs[(size_t)Kk * Tt * Bb * Hh];          // [k][t][b][h]

// ---------------- helpers ----------------
__device__ __forceinline__ uint32_t smem_u32(const void* p) {
    uint32_t a;
    asm("{ .reg .u64 t; cvta.to.shared.u64 t, %1; cvt.u32.u64 %0, t; }" : "=r"(a) : "l"(p));
    return a;
}
__device__ __forceinline__ void cp16(uint32_t saddr, const void* g) {
    asm volatile("cp.async.cg.shared.global [%0], [%1], 16;" :: "r"(saddr), "l"(g));
}
__device__ __forceinline__ void cp_commit() {
    asm volatile("cp.async.commit_group;" ::: "memory");
}
template <int N> __device__ __forceinline__ void cp_wait() {
    asm volatile("cp.async.wait_group %0;" :: "n"(N) : "memory");
}
__device__ __forceinline__ void ldsm_x4(uint32_t a, uint32_t* r) {
    asm volatile("ldmatrix.sync.aligned.m8n8.x4.shared.b16 {%0,%1,%2,%3}, [%4];"
                 : "=r"(r[0]), "=r"(r[1]), "=r"(r[2]), "=r"(r[3]) : "r"(a));
}
__device__ __forceinline__ void mma16816(float* d, const uint32_t* a, const uint32_t* b) {
    asm volatile(
        "mma.sync.aligned.m16n8k16.row.col.f32.bf16.bf16.f32 "
        "{%0,%1,%2,%3}, {%4,%5,%6,%7}, {%8,%9}, {%0,%1,%2,%3};"
        : "+f"(d[0]), "+f"(d[1]), "+f"(d[2]), "+f"(d[3])
        : "r"(a[0]), "r"(a[1]), "r"(a[2]), "r"(a[3]), "r"(b[0]), "r"(b[1]));
}
__device__ __forceinline__ float sigm(float x) { return 1.f / (1.f + expf(-x)); }

// swizzle for 64B rows: chunk (0..3) ^= (row>>1)&3
__device__ __forceinline__ uint32_t swz64(int r, int c) {
    return (uint32_t)(r * 64 + ((c ^ ((r >> 1) & 3)) << 4));
}
// swizzle for 32B rows (k-chunk 16), chunk (0..1) ^= (row>>2)&1
__device__ __forceinline__ uint32_t swz32(int r, int c) {
    return (uint32_t)(r * 32 + ((c ^ ((r >> 2) & 1)) << 4));
}

// ---------------- data transpose + split: [B,F,T] -> bf16 hi/lo [T,B,F] ----------------
__global__ void transpose_data(const float* __restrict__ data) {
    int idx = blockIdx.x * blockDim.x + threadIdx.x;
    if (idx >= Tt * Bb * Ff) return;
    int f = idx % Ff;
    int b = (idx / Ff) % Bb;
    int t = idx / (Ff * Bb);
    float v = data[(size_t)b * Ff * Tt + (size_t)f * Tt + t];
    __nv_bfloat16 hi = __float2bfloat16(v);
    g_dh[idx] = hi;
    g_dl[idx] = __float2bfloat16(v - __bfloat162float(hi));
}

// ---------------- weight splitting (Wih, Whh, fc_in_W) ----------------
__global__ void split_w3(const float* __restrict__ Wih, const float* __restrict__ Whh,
                         const float* __restrict__ fcW) {
    const int NW = Kk * NN * Hh;
    const int NF = Kk * Hh * Ff;
    int idx = blockIdx.x * 256 + threadIdx.x;
    if (idx < NW) {
        float v = Wih[idx];
        __nv_bfloat16 hi = __float2bfloat16(v);
        g_Wih_h[idx] = hi;
        g_Wih_l[idx] = __float2bfloat16(v - __bfloat162float(hi));
    } else if (idx < 2 * NW) {
        int i = idx - NW;
        float v = Whh[i];
        __nv_bfloat16 hi = __float2bfloat16(v);
        g_Whh_h[i] = hi;
        g_Whh_l[i] = __float2bfloat16(v - __bfloat162float(hi));
    } else if (idx < 2 * NW + NF) {
        int i = idx - 2 * NW;
        float v = fcW[i];
        __nv_bfloat16 hi = __float2bfloat16(v);
        g_fcW_h[i] = hi;
        g_fcW_l[i] = __float2bfloat16(v - __bfloat162float(hi));
    }
}

// ---------------- h init (+ split) ----------------
__global__ void init_h_kernel(const float* __restrict__ init) {
    int idx = blockIdx.x * 256 + threadIdx.x;   // K*B*H
    float v = init[idx % (Bb * Hh)];
    g_h[idx] = v;
    __nv_bfloat16 hi = __float2bfloat16(v);
    g_hh[idx] = hi;
    g_hl[idx] = __float2bfloat16(v - __bfloat162float(hi));
}

// ---------------- proj: bf16x3 HMMA, M128 x N128, K=64 -> relu + split ----------------
// A rows = data[tt][b][f] (tt reversed for cells 2,3); B rows = fc_in_W[k][h][f].
__global__ void __launch_bounds__(256, 1) proj_hmma(const float* __restrict__ fcB) {
    // stage 16KB: A_hi[0,4K) A_lo[4K,8K) B_hi[8K,12K) B_lo[12K,16K); 2 stages
    __shared__ __align__(16) char smem[32768];
    uint32_t sb = smem_u32(smem);
    int tid = threadIdx.x, wid = tid >> 5, lane = tid & 31;
    int z = blockIdx.z;
    int n0 = blockIdx.x * 128, m0 = blockIdx.y * 128;
    int warp_m = wid >> 2, warp_n = wid & 3;      // warp tile 64 x 32
    int t = m0 >> 9, b0 = m0 & 511;
    int tt = (z < 2) ? t : (Tt - 1 - t);

    const __nv_bfloat16* Ah = g_dh + ((size_t)tt * Bb + b0) * Ff;
    const __nv_bfloat16* Al = g_dl + ((size_t)tt * Bb + b0) * Ff;
    const __nv_bfloat16* Bh = g_fcW_h + (size_t)z * Hh * Ff;
    const __nv_bfloat16* Bl = g_fcW_l + (size_t)z * Hh * Ff;

    float acc[4][4][4];
#pragma unroll
    for (int i = 0; i < 4; i++)
#pragma unroll
        for (int j = 0; j < 4; j++)
#pragma unroll
            for (int q = 0; q < 4; q++) acc[i][j][q] = 0.f;

    auto load_stage = [&](int s, int k0) {
        uint32_t st = sb + s * 16384;
#pragma unroll
        for (int i = 0; i < 4; i++) {
            int idx = tid + i * 256;           // 0..1023
            if (idx < 512) {                   // A hi/lo, 256 chunks each
                bool hi = idx < 256;
                int li = idx & 255;
                int r = li >> 1, c = li & 1;
                cp16(st + (hi ? 0 : 4096) + swz32(r, c),
                     (hi ? Ah : Al) + (size_t)r * Ff + k0 + c * 8);
            } else {                           // B hi/lo
                int li = idx - 512;
                bool hi = li < 256;
                li &= 255;
                int r = li >> 1, c = li & 1;
                cp16(st + 8192 + (hi ? 0 : 4096) + swz32(r, c),
                     (hi ? Bh : Bl) + (size_t)(n0 + r) * Ff + k0 + c * 8);
            }
        }
        cp_commit();
    };

    load_stage(0, 0);
    int cfr = lane >> 4;
    for (int kc = 0; kc < 4; kc++) {
        if (kc + 1 < 4) { load_stage((kc + 1) & 1, (kc + 1) * 16); cp_wait<1>(); }
        else cp_wait<0>();
        __syncthreads();
        uint32_t st = sb + (uint32_t)(kc & 1) * 16384;
        uint32_t a_h[4][4], a_l[4][4], b_h[4][2], b_l[4][2];
#pragma unroll
        for (int mi = 0; mi < 4; mi++) {
            int rA = warp_m * 64 + mi * 16 + (lane & 15);
            uint32_t ad = st + swz32(rA, cfr);
            ldsm_x4(ad, a_h[mi]);
            ldsm_x4(ad + 4096, a_l[mi]);
        }
#pragma unroll
        for (int nj = 0; nj < 2; nj++) {
            int rB = warp_n * 32 + nj * 16 + (lane & 15);
            uint32_t bd = st + 8192 + swz32(rB, cfr);
            uint32_t r4[4];
            ldsm_x4(bd, r4);
            b_h[2 * nj][0] = r4[0]; b_h[2 * nj][1] = r4[2];
            b_h[2 * nj + 1][0] = r4[1]; b_h[2 * nj + 1][1] = r4[3];
            ldsm_x4(bd + 4096, r4);
            b_l[2 * nj][0] = r4[0]; b_l[2 * nj][1] = r4[2];
            b_l[2 * nj + 1][0] = r4[1]; b_l[2 * nj + 1][1] = r4[3];
        }
#pragma unroll
        for (int mi = 0; mi < 4; mi++)
#pragma unroll
            for (int ni = 0; ni < 4; ni++) {
                mma16816(acc[mi][ni], a_h[mi], b_h[ni]);
                mma16816(acc[mi][ni], a_h[mi], b_l[ni]);
                mma16816(acc[mi][ni], a_l[mi], b_h[ni]);
            }
        __syncthreads();
    }

    int lane4 = lane >> 2;
    int cp2 = 2 * (lane & 3);
    const float* bz = fcB + (size_t)z * Hh;
#pragma unroll
    for (int mi = 0; mi < 4; mi++)
#pragma unroll
        for (int v = 0; v < 2; v++) {
            int rl = warp_m * 64 + mi * 16 + lane4 + 8 * v;
            size_t rowoff = (((size_t)z * Tt + t) * Bb + (b0 + rl)) * Hh;
#pragma unroll
            for (int ni = 0; ni < 4; ni++) {
                int h = n0 + warp_n * 32 + ni * 8 + cp2;
                int q = 2 * v;
                float v0 = fmaxf(acc[mi][ni][q] + bz[h], 0.f);
                float v1 = fmaxf(acc[mi][ni][q + 1] + bz[h + 1], 0.f);
                __nv_bfloat162 hv, lv;
                hv.x = __float2bfloat16(v0);
                hv.y = __float2bfloat16(v1);
                lv.x = __float2bfloat16(v0 - __bfloat162float(hv.x));
                lv.y = __float2bfloat16(v1 - __bfloat162float(hv.y));
                *(__nv_bfloat162*)(g_xh + rowoff + h) = hv;
                *(__nv_bfloat162*)(g_xl + rowoff + h) = lv;
            }
        }
}

// ---------------- HMMA bf16x3 NT GEMM + bias (round-5 geometry, 48KB static) ----------
// C[m][n] = sum_i A[m][i]*W[n][i] + bias[n], via Ah*Bh + Ah*Bl + Al*Bh
// CTA tile 128(M) x 64(N), k-chunk 32, double buffered; warp tile 32x32; 2 CTAs/SM.
// grid: (NN/64, M/128, Kk) -- n fastest for A-tile L2 reuse
template <int MODE>
__global__ void __launch_bounds__(256, 1) gemm_hmma(const float* __restrict__ biasb) {
    // per-stage layout: A_h[0,8K) A_l[8K,16K) B_h[16K,20K) B_l[20K,24K)
    __shared__ __align__(16) char smem[49152];
    const int A_LO = 8192, B_HI = 16384, B_LO = 20480, STAGE = 24576;

    int tid = threadIdx.x, wid = tid >> 5, lane = tid & 31;
    int z = blockIdx.z;
    int n0 = blockIdx.x * 64, m0 = blockIdx.y * 128;

    const __nv_bfloat16* Ah = (MODE == 0 ? g_xh : g_hh) +
        (size_t)z * (MODE == 0 ? (size_t)Tt * Bb * Hh : (size_t)Bb * Hh);
    const __nv_bfloat16* Al = (MODE == 0 ? g_xl : g_hl) +
        (size_t)z * (MODE == 0 ? (size_t)Tt * Bb * Hh : (size_t)Bb * Hh);
    const __nv_bfloat16* Bh = (MODE == 0 ? g_Wih_h : g_Whh_h) + (size_t)z * NN * Hh;
    const __nv_bfloat16* Bl = (MODE == 0 ? g_Wih_l : g_Whh_l) + (size_t)z * NN * Hh;
    float* C = (MODE == 0 ? g_gi : g_gh) +
        (size_t)z * (MODE == 0 ? (size_t)Tt * Bb * NN : (size_t)Bb * NN);
    const float* bias = biasb + (size_t)z * NN;

    uint32_t sb = smem_u32(smem);
    int warp_m = wid >> 1;     // 4 warps over M (32 rows each)
    int warp_n = wid & 1;      // 2 warps over N (32 cols each)

    float acc[2][4][4];
#pragma unroll
    for (int i = 0; i < 2; i++)
#pragma unroll
        for (int j = 0; j < 4; j++)
#pragma unroll
            for (int q = 0; q < 4; q++) acc[i][j][q] = 0.f;

    // stage loader: A 128x32 (hi+lo), B 64x32 (hi+lo); 1536 16B chunks / 256 thr = 6
    auto load_stage = [&](int s, int k0) {
        uint32_t st = sb + s * STAGE;
#pragma unroll
        for (int i = 0; i < 6; i++) {
            int idx = tid + i * 256;            // 0..1535
            if (idx < 1024) {                   // A hi (0..511) / A lo (512..1023)
                int r = (idx & 511) >> 2;
                int c = idx & 3;
                uint32_t so = st + (idx < 512 ? 0 : A_LO) + swz64(r, c);
                const __nv_bfloat16* g = (idx < 512 ? Ah : Al) + (size_t)(m0 + r) * Hh + k0 + c * 8;
                cp16(so, g);
            } else {                            // B hi (1024..1279) / B lo (1280..1535)
                int li = idx - 1024;
                int r = (li & 255) >> 2;
                int c = li & 3;
                uint32_t so = st + (li < 256 ? B_HI : B_LO) + swz64(r, c);
                const __nv_bfloat16* g = (li < 256 ? Bh : Bl) + (size_t)(n0 + r) * Hh + k0 + c * 8;
                cp16(so, g);
            }
        }
        cp_commit();
    };

    load_stage(0, 0);

    for (int kc = 0; kc < 16; kc++) {
        if (kc < 15) { load_stage((kc + 1) & 1, (kc + 1) * 32); cp_wait<1>(); }
        else cp_wait<0>();
        __syncthreads();

        uint32_t st = sb + (kc & 1) * STAGE;
#pragma unroll
        for (int ks = 0; ks < 2; ks++) {
            uint32_t a_h[2][4], a_l[2][4], b_h[4][2], b_l[4][2];
            int chunk = ks * 2 + (lane >> 4);   // 16B chunk index within 64B row
            // A fragments: 2 m-tiles of 16 rows
#pragma unroll
            for (int mi = 0; mi < 2; mi++) {
                int rr = warp_m * 32 + mi * 16 + (lane & 15);
                uint32_t ad = st + swz64(rr, chunk);
                ldsm_x4(ad, a_h[mi]);
                ldsm_x4(ad + A_LO, a_l[mi]);
            }
            // B fragments: 2 ldmatrix.x4 over 16 n-rows each -> 4 n-tiles of 8
#pragma unroll
            for (int nj = 0; nj < 2; nj++) {
                int rr = warp_n * 32 + nj * 16 + (lane & 15);
                uint32_t bd = st + B_HI + swz64(rr, chunk);
                uint32_t r4[4];
                ldsm_x4(bd, r4);
                b_h[2 * nj][0] = r4[0]; b_h[2 * nj][1] = r4[2];
                b_h[2 * nj + 1][0] = r4[1]; b_h[2 * nj + 1][1] = r4[3];
                ldsm_x4(bd + 4096, r4);   // B_LO = B_HI + 4096
                b_l[2 * nj][0] = r4[0]; b_l[2 * nj][1] = r4[2];
                b_l[2 * nj + 1][0] = r4[1]; b_l[2 * nj + 1][1] = r4[3];
            }
#pragma unroll
            for (int mi = 0; mi < 2; mi++)
#pragma unroll
                for (int ni = 0; ni < 4; ni++) {
                    mma16816(acc[mi][ni], a_h[mi], b_h[ni]);
                    mma16816(acc[mi][ni], a_h[mi], b_l[ni]);
                    mma16816(acc[mi][ni], a_l[mi], b_h[ni]);
                }
        }
        __syncthreads();
    }

    // epilogue: write C + bias
#pragma unroll
    for (int mi = 0; mi < 2; mi++) {
        int row = m0 + warp_m * 32 + mi * 16 + (lane >> 2);
#pragma unroll
        for (int ni = 0; ni < 4; ni++) {
            int col = n0 + warp_n * 32 + ni * 8 + 2 * (lane & 3);
            float2 o0, o1;
            o0.x = acc[mi][ni][0] + bias[col];
            o0.y = acc[mi][ni][1] + bias[col + 1];
            o1.x = acc[mi][ni][2] + bias[col];
            o1.y = acc[mi][ni][3] + bias[col + 1];
            *(float2*)(C + (size_t)row * NN + col) = o0;
            *(float2*)(C + (size_t)(row + 8) * NN + col) = o1;
        }
    }
}

// ---------------- GRU gate update (per step) + h split ----------------
__global__ void gru_gates(int t) {
    int idx = blockIdx.x * 256 + threadIdx.x;   // over K*B*H
    int k = idx / (Bb * Hh);
    int rem = idx - k * (Bb * Hh);
    int b = rem / Hh;
    int hh = rem - b * Hh;
    const float* gik = g_gi + (((size_t)k * Tt + t) * Bb + b) * NN;
    const float* ghk = g_gh + ((size_t)k * Bb + b) * NN;
    float r = sigm(gik[hh] + ghk[hh]);
    float z = sigm(gik[Hh + hh] + ghk[Hh + hh]);
    float n = tanhf(gik[2 * Hh + hh] + r * ghk[2 * Hh + hh]);
    float hp = g_h[idx];
    float hnew = (1.f - z) * n + z * hp;
    g_h[idx] = hnew;
    g_hs[(((size_t)k * Tt + t) * Bb + b) * Hh + hh] = hnew;
    __nv_bfloat16 hi = __float2bfloat16(hnew);
    g_hh[idx] = hi;
    g_hl[idx] = __float2bfloat16(hnew - __bfloat162float(hi));
}

// ---------------- output heads ----------------
__global__ void out_kernel(const float* __restrict__ Wout,
                           const float* __restrict__ bout,
                           float* __restrict__ out) {
    int warp = threadIdx.x >> 5;
    int lane = threadIdx.x & 31;
    int oid = blockIdx.x * 8 + warp;
    int pair = oid >> 15;
    int rem = oid & 32767;
    int b = rem >> 6;
    int t = rem & 63;
    const float* hf = g_hs + (((size_t)pair * Tt + t) * Bb + b) * Hh;
    const float* hb = g_hs + (((size_t)(pair + 2) * Tt + (Tt - 1 - t)) * Bb + b) * Hh;
    const float* w = Wout + pair * Hh;
    float s = 0.f;
    for (int i0 = lane * 4; i0 < Hh; i0 += 128) {
        float4 f = *(const float4*)(hf + i0);
        float4 g = *(const float4*)(hb + i0);
        float4 wv = *(const float4*)(w + i0);
        s += (f.x + g.x) * wv.x + (f.y + g.y) * wv.y +
             (f.z + g.z) * wv.z + (f.w + g.w) * wv.w;
    }
#pragma unroll
    for (int o = 16; o; o >>= 1) s += __shfl_xor_sync(0xffffffffu, s, o);
    if (lane == 0) out[(size_t)pair * Bb * Tt + b * Tt + t] = s + bout[pair];
}

// ---------------- launch (kernel launches ONLY) ----------------
extern "C" void kernel_launch(void* const* d_in, const int* in_sizes, int n_in,
                              void* d_out, int out_size) {
    const float* data     = (const float*)d_in[0];
    const float* init     = (const float*)d_in[1];
    const float* fc_in_W  = (const float*)d_in[2];
    const float* fc_in_b  = (const float*)d_in[3];
    const float* Wih      = (const float*)d_in[4];
    const float* Whh      = (const float*)d_in[5];
    const float* bih      = (const float*)d_in[6];
    const float* bhh      = (const float*)d_in[7];
    const float* fc_out_W = (const float*)d_in[8];
    const float* fc_out_b = (const float*)d_in[9];
    float* out = (float*)d_out;

    transpose_data<<<(Tt * Bb * Ff) / 256, 256>>>(data);
    split_w3<<<(2 * Kk * NN * Hh + Kk * Hh * Ff) / 256, 256>>>(Wih, Whh, fc_in_W);

    // proj (HMMA): M = T*B per cell, N = 512, K = 64
    proj_hmma<<<dim3(Hh / 128, (Tt * Bb) / 128, Kk), 256>>>(fc_in_b);

    // gi = xseq @ Wih^T + bih : M = T*B = 32768
    gemm_hmma<0><<<dim3(NN / 64, (Tt * Bb) / 128, Kk), 256>>>(bih);

    init_h_kernel<<<(Kk * Bb * Hh) / 256, 256>>>(init);

    for (int t = 0; t < Tt; t++) {
        // gh = h @ Whh^T + bhh : M = B = 512
        gemm_hmma<1><<<dim3(NN / 64, Bb / 128, Kk), 256>>>(bhh);
        gru_gates<<<(Kk * Bb * Hh) / 256, 256>>>(t);
    }

    out_kernel<<<(2 * Bb * Tt) / 8, 256>>>(fc_out_W, fc_out_b, out);
}

// round 12
// speedup vs baseline: 2.2539x; 1.8800x over previous
#include <cuda_runtime.h>
#include <cuda_fp16.h>
#include <math.h>
#include <stdint.h>

#define Bb 512
#define Ff 64
#define Tt 64
#define Hh 512
#define Kk 4
#define NN (3 * Hh)   // 1536

// ---------------- scratch (static device globals; no allocation) ----------------
__device__ __align__(16) __half g_d[(size_t)Tt * Bb * Ff];        // data fp16 [t][b][f]
__device__ __align__(16) __half g_fcW[(size_t)Kk * Hh * Ff];
__device__ __align__(16) __half g_x[(size_t)Kk * Tt * Bb * Hh];   // x fp16
__device__ __align__(16) __half g_Wih[(size_t)Kk * NN * Hh];
__device__ __align__(16) __half g_Whh[(size_t)Kk * NN * Hh];
__device__ __align__(16) __half g_hf[(size_t)Kk * Bb * Hh];       // h fp16 (GEMM operand)
__device__ __align__(16) float g_gi[(size_t)Kk * Tt * Bb * NN];   // [k][(t,b)][3H]
__device__ __align__(16) float g_gh[(size_t)Kk * Bb * NN];        // [k][b][3H]
__device__ __align__(16) float g_h[(size_t)Kk * Bb * Hh];         // h fp32 (recurrence)
__device__ __align__(16) float g_hs[(size_t)Kk * Tt * Bb * Hh];   // [k][t][b][h]

// ---------------- helpers ----------------
__device__ __forceinline__ uint32_t smem_u32(const void* p) {
    uint32_t a;
    asm("{ .reg .u64 t; cvta.to.shared.u64 t, %1; cvt.u32.u64 %0, t; }" : "=r"(a) : "l"(p));
    return a;
}
__device__ __forceinline__ void cp16(uint32_t saddr, const void* g) {
    asm volatile("cp.async.cg.shared.global [%0], [%1], 16;" :: "r"(saddr), "l"(g));
}
__device__ __forceinline__ void cp_commit() {
    asm volatile("cp.async.commit_group;" ::: "memory");
}
template <int N> __device__ __forceinline__ void cp_wait() {
    asm volatile("cp.async.wait_group %0;" :: "n"(N) : "memory");
}
__device__ __forceinline__ void ldsm_x4(uint32_t a, uint32_t* r) {
    asm volatile("ldmatrix.sync.aligned.m8n8.x4.shared.b16 {%0,%1,%2,%3}, [%4];"
                 : "=r"(r[0]), "=r"(r[1]), "=r"(r[2]), "=r"(r[3]) : "r"(a));
}
__device__ __forceinline__ void mma16816(float* d, const uint32_t* a, const uint32_t* b) {
    asm volatile(
        "mma.sync.aligned.m16n8k16.row.col.f32.f16.f16.f32 "
        "{%0,%1,%2,%3}, {%4,%5,%6,%7}, {%8,%9}, {%0,%1,%2,%3};"
        : "+f"(d[0]), "+f"(d[1]), "+f"(d[2]), "+f"(d[3])
        : "r"(a[0]), "r"(a[1]), "r"(a[2]), "r"(a[3]), "r"(b[0]), "r"(b[1]));
}
__device__ __forceinline__ float sigm(float x) { return 1.f / (1.f + expf(-x)); }

// swizzle for 64B rows (k-chunk 32 fp16): chunk (0..3) ^= (row>>1)&3
__device__ __forceinline__ uint32_t swz64(int r, int c) {
    return (uint32_t)(r * 64 + ((c ^ ((r >> 1) & 3)) << 4));
}
// swizzle for 32B rows (k-chunk 16 fp16): chunk (0..1) ^= (row>>2)&1
__device__ __forceinline__ uint32_t swz32(int r, int c) {
    return (uint32_t)(r * 32 + ((c ^ ((r >> 2) & 1)) << 4));
}

// ---------------- data transpose: [B,F,T] -> fp16 [T,B,F] ----------------
__global__ void transpose_data(const float* __restrict__ data) {
    int idx = blockIdx.x * blockDim.x + threadIdx.x;
    if (idx >= Tt * Bb * Ff) return;
    int f = idx % Ff;
    int b = (idx / Ff) % Bb;
    int t = idx / (Ff * Bb);
    g_d[idx] = __float2half(data[(size_t)b * Ff * Tt + (size_t)f * Tt + t]);
}

// ---------------- weight conversion (Wih, Whh, fc_in_W) -> fp16 ----------------
__global__ void convert_w(const float* __restrict__ Wih, const float* __restrict__ Whh,
                          const float* __restrict__ fcW) {
    const int NW = Kk * NN * Hh;
    const int NF = Kk * Hh * Ff;
    int idx = blockIdx.x * 256 + threadIdx.x;
    if (idx < NW) {
        g_Wih[idx] = __float2half(Wih[idx]);
    } else if (idx < 2 * NW) {
        g_Whh[idx - NW] = __float2half(Whh[idx - NW]);
    } else if (idx < 2 * NW + NF) {
        g_fcW[idx - 2 * NW] = __float2half(fcW[idx - 2 * NW]);
    }
}

// ---------------- h init ----------------
__global__ void init_h_kernel(const float* __restrict__ init) {
    int idx = blockIdx.x * 256 + threadIdx.x;   // K*B*H
    float v = init[idx % (Bb * Hh)];
    g_h[idx] = v;
    g_hf[idx] = __float2half(v);
}

// ---------------- proj: fp16 HMMA, M128 x N128, K=64 -> relu -> g_x ----------------
__global__ void __launch_bounds__(256, 2) proj_hmma(const float* __restrict__ fcB) {
    // stage 8KB: A[0,4K) B[4K,8K); 2 stages = 16KB
    __shared__ __align__(16) char smem[16384];
    uint32_t sb = smem_u32(smem);
    int tid = threadIdx.x, wid = tid >> 5, lane = tid & 31;
    int z = blockIdx.z;
    int n0 = blockIdx.x * 128, m0 = blockIdx.y * 128;
    int warp_m = wid >> 2, warp_n = wid & 3;      // warp tile 64 x 32
    int t = m0 >> 9, b0 = m0 & 511;
    int tt = (z < 2) ? t : (Tt - 1 - t);

    const __half* A = g_d + ((size_t)tt * Bb + b0) * Ff;
    const __half* Bw = g_fcW + (size_t)z * Hh * Ff;

    float acc[4][4][4];
#pragma unroll
    for (int i = 0; i < 4; i++)
#pragma unroll
        for (int j = 0; j < 4; j++)
#pragma unroll
            for (int q = 0; q < 4; q++) acc[i][j][q] = 0.f;

    // 512 16B chunks / 256 threads = 2
    auto load_stage = [&](int s, int k0) {
        uint32_t st = sb + s * 8192;
#pragma unroll
        for (int i = 0; i < 2; i++) {
            int idx = tid + i * 256;           // 0..511
            bool isA = idx < 256;
            int li = idx & 255;
            int r = li >> 1, c = li & 1;
            cp16(st + (isA ? 0 : 4096) + swz32(r, c),
                 (isA ? A : Bw) + (size_t)(isA ? r : n0 + r) * Ff + k0 + c * 8);
        }
        cp_commit();
    };

    load_stage(0, 0);
    int cfr = lane >> 4;
    for (int kc = 0; kc < 4; kc++) {
        if (kc + 1 < 4) { load_stage((kc + 1) & 1, (kc + 1) * 16); cp_wait<1>(); }
        else cp_wait<0>();
        __syncthreads();
        uint32_t st = sb + (uint32_t)(kc & 1) * 8192;
        uint32_t a_f[4][4], b_f[4][2];
#pragma unroll
        for (int mi = 0; mi < 4; mi++) {
            int rA = warp_m * 64 + mi * 16 + (lane & 15);
            ldsm_x4(st + swz32(rA, cfr), a_f[mi]);
        }
#pragma unroll
        for (int nj = 0; nj < 2; nj++) {
            int rB = warp_n * 32 + nj * 16 + (lane & 15);
            uint32_t r4[4];
            ldsm_x4(st + 4096 + swz32(rB, cfr), r4);
            b_f[2 * nj][0] = r4[0]; b_f[2 * nj][1] = r4[2];
            b_f[2 * nj + 1][0] = r4[1]; b_f[2 * nj + 1][1] = r4[3];
        }
#pragma unroll
        for (int mi = 0; mi < 4; mi++)
#pragma unroll
            for (int ni = 0; ni < 4; ni++)
                mma16816(acc[mi][ni], a_f[mi], b_f[ni]);
        __syncthreads();
    }

    int lane4 = lane >> 2;
    int cp2 = 2 * (lane & 3);
    const float* bz = fcB + (size_t)z * Hh;
#pragma unroll
    for (int mi = 0; mi < 4; mi++)
#pragma unroll
        for (int v = 0; v < 2; v++) {
            int rl = warp_m * 64 + mi * 16 + lane4 + 8 * v;
            size_t rowoff = (((size_t)z * Tt + t) * Bb + (b0 + rl)) * Hh;
#pragma unroll
            for (int ni = 0; ni < 4; ni++) {
                int h = n0 + warp_n * 32 + ni * 8 + cp2;
                int q = 2 * v;
                __half2 hv;
                hv.x = __float2half(fmaxf(acc[mi][ni][q] + bz[h], 0.f));
                hv.y = __float2half(fmaxf(acc[mi][ni][q + 1] + bz[h + 1], 0.f));
                *(__half2*)(g_x + rowoff + h) = hv;
            }
        }
}

// ---------------- fp16 NT GEMM + bias: CTA 128x128, warp 32x64, k-chunk 32 ----------
// C[m][n] = sum_i A[m][i]*W[n][i] + bias[n]
// MODE 0: A = g_x (M = T*B), C = g_gi.  MODE 1: A = g_hf (M = B), C = g_gh.
// grid: (NN/128, M/128, Kk) -- n fastest for A-tile L2 reuse
template <int MODE>
__global__ void __launch_bounds__(256, 2) gemm_hmma(const float* __restrict__ biasb) {
    // stage 16KB: A[0,8K) B[8K,16K); 2 stages = 32KB
    __shared__ __align__(16) char smem[32768];
    uint32_t sb = smem_u32(smem);

    int tid = threadIdx.x, wid = tid >> 5, lane = tid & 31;
    int z = blockIdx.z;
    int n0 = blockIdx.x * 128, m0 = blockIdx.y * 128;
    int warp_m = wid >> 1;     // 4 warps over M (32 rows each)
    int warp_n = wid & 1;      // 2 warps over N (64 cols each)

    const __half* A = (MODE == 0 ? g_x : g_hf) +
        (size_t)z * (MODE == 0 ? (size_t)Tt * Bb * Hh : (size_t)Bb * Hh);
    const __half* Bw = (MODE == 0 ? g_Wih : g_Whh) + (size_t)z * NN * Hh;
    float* C = (MODE == 0 ? g_gi : g_gh) +
        (size_t)z * (MODE == 0 ? (size_t)Tt * Bb * NN : (size_t)Bb * NN);
    const float* bias = biasb + (size_t)z * NN;

    float acc[2][8][4];
#pragma unroll
    for (int i = 0; i < 2; i++)
#pragma unroll
        for (int j = 0; j < 8; j++)
#pragma unroll
            for (int q = 0; q < 4; q++) acc[i][j][q] = 0.f;

    // 1024 16B chunks per stage / 256 threads = 4
    auto load_stage = [&](int s, int k0) {
        uint32_t st = sb + s * 16384;
#pragma unroll
        for (int i = 0; i < 4; i++) {
            int idx = tid + i * 256;            // 0..1023
            bool isA = idx < 512;
            int li = idx & 511;
            int r = li >> 2, c = li & 3;
            cp16(st + (isA ? 0 : 8192) + swz64(r, c),
                 (isA ? A : Bw) + (size_t)((isA ? m0 : n0) + r) * Hh + k0 + c * 8);
        }
        cp_commit();
    };

    load_stage(0, 0);

    for (int kc = 0; kc < 16; kc++) {
        if (kc < 15) { load_stage((kc + 1) & 1, (kc + 1) * 32); cp_wait<1>(); }
        else cp_wait<0>();
        __syncthreads();

        uint32_t st = sb + (uint32_t)(kc & 1) * 16384;
#pragma unroll
        for (int ks = 0; ks < 2; ks++) {
            uint32_t a_f[2][4], b_f[8][2];
            int chunk = ks * 2 + (lane >> 4);   // 16B chunk index within 64B row
#pragma unroll
            for (int mi = 0; mi < 2; mi++) {
                int rr = warp_m * 32 + mi * 16 + (lane & 15);
                ldsm_x4(st + swz64(rr, chunk), a_f[mi]);
            }
#pragma unroll
            for (int nj = 0; nj < 4; nj++) {
                int rr = warp_n * 64 + nj * 16 + (lane & 15);
                uint32_t r4[4];
                ldsm_x4(st + 8192 + swz64(rr, chunk), r4);
                b_f[2 * nj][0] = r4[0]; b_f[2 * nj][1] = r4[2];
                b_f[2 * nj + 1][0] = r4[1]; b_f[2 * nj + 1][1] = r4[3];
            }
#pragma unroll
            for (int mi = 0; mi < 2; mi++)
#pragma unroll
                for (int ni = 0; ni < 8; ni++)
                    mma16816(acc[mi][ni], a_f[mi], b_f[ni]);
        }
        __syncthreads();
    }

    // epilogue: write C + bias
#pragma unroll
    for (int mi = 0; mi < 2; mi++) {
        int row = m0 + warp_m * 32 + mi * 16 + (lane >> 2);
#pragma unroll
        for (int ni = 0; ni < 8; ni++) {
            int col = n0 + warp_n * 64 + ni * 8 + 2 * (lane & 3);
            float2 o0, o1;
            o0.x = acc[mi][ni][0] + bias[col];
            o0.y = acc[mi][ni][1] + bias[col + 1];
            o1.x = acc[mi][ni][2] + bias[col];
            o1.y = acc[mi][ni][3] + bias[col + 1];
            *(float2*)(C + (size_t)row * NN + col) = o0;
            *(float2*)(C + (size_t)(row + 8) * NN + col) = o1;
        }
    }
}

// ---------------- GRU gate update (per step) ----------------
__global__ void gru_gates(int t) {
    int idx = blockIdx.x * 256 + threadIdx.x;   // over K*B*H
    int k = idx / (Bb * Hh);
    int rem = idx - k * (Bb * Hh);
    int b = rem / Hh;
    int hh = rem - b * Hh;
    const float* gik = g_gi + (((size_t)k * Tt + t) * Bb + b) * NN;
    const float* ghk = g_gh + ((size_t)k * Bb + b) * NN;
    float r = sigm(gik[hh] + ghk[hh]);
    float z = sigm(gik[Hh + hh] + ghk[Hh + hh]);
    float n = tanhf(gik[2 * Hh + hh] + r * ghk[2 * Hh + hh]);
    float hp = g_h[idx];
    float hnew = (1.f - z) * n + z * hp;
    g_h[idx] = hnew;
    g_hs[(((size_t)k * Tt + t) * Bb + b) * Hh + hh] = hnew;
    g_hf[idx] = __float2half(hnew);
}

// ---------------- output heads ----------------
__global__ void out_kernel(const float* __restrict__ Wout,
                           const float* __restrict__ bout,
                           float* __restrict__ out) {
    int warp = threadIdx.x >> 5;
    int lane = threadIdx.x & 31;
    int oid = blockIdx.x * 8 + warp;
    int pair = oid >> 15;
    int rem = oid & 32767;
    int b = rem >> 6;
    int t = rem & 63;
    const float* hf = g_hs + (((size_t)pair * Tt + t) * Bb + b) * Hh;
    const float* hb = g_hs + (((size_t)(pair + 2) * Tt + (Tt - 1 - t)) * Bb + b) * Hh;
    const float* w = Wout + pair * Hh;
    float s = 0.f;
    for (int i0 = lane * 4; i0 < Hh; i0 += 128) {
        float4 f = *(const float4*)(hf + i0);
        float4 g = *(const float4*)(hb + i0);
        float4 wv = *(const float4*)(w + i0);
        s += (f.x + g.x) * wv.x + (f.y + g.y) * wv.y +
             (f.z + g.z) * wv.z + (f.w + g.w) * wv.w;
    }
#pragma unroll
    for (int o = 16; o; o >>= 1) s += __shfl_xor_sync(0xffffffffu, s, o);
    if (lane == 0) out[(size_t)pair * Bb * Tt + b * Tt + t] = s + bout[pair];
}

// ---------------- launch (kernel launches ONLY) ----------------
extern "C" void kernel_launch(void* const* d_in, const int* in_sizes, int n_in,
                              void* d_out, int out_size) {
    const float* data     = (const float*)d_in[0];
    const float* init     = (const float*)d_in[1];
    const float* fc_in_W  = (const float*)d_in[2];
    const float* fc_in_b  = (const float*)d_in[3];
    const float* Wih      = (const float*)d_in[4];
    const float* Whh      = (const float*)d_in[5];
    const float* bih      = (const float*)d_in[6];
    const float* bhh      = (const float*)d_in[7];
    const float* fc_out_W = (const float*)d_in[8];
    const float* fc_out_b = (const float*)d_in[9];
    float* out = (float*)d_out;

    transpose_data<<<(Tt * Bb * Ff) / 256, 256>>>(data);
    convert_w<<<(2 * Kk * NN * Hh + Kk * Hh * Ff) / 256, 256>>>(Wih, Whh, fc_in_W);

    // proj (fp16 HMMA): M = T*B per cell, N = 512, K = 64
    proj_hmma<<<dim3(Hh / 128, (Tt * Bb) / 128, Kk), 256>>>(fc_in_b);

    // gi = xseq @ Wih^T + bih : M = T*B = 32768
    gemm_hmma<0><<<dim3(NN / 128, (Tt * Bb) / 128, Kk), 256>>>(bih);

    init_h_kernel<<<(Kk * Bb * Hh) / 256, 256>>>(init);

    for (int t = 0; t < Tt; t++) {
        // gh = h @ Whh^T + bhh : M = B = 512
        gemm_hmma<1><<<dim3(NN / 128, Bb / 128, Kk), 256>>>(bhh);
        gru_gates<<<(Kk * Bb * Hh) / 256, 256>>>(t);
    }

    out_kernel<<<(2 * Bb * Tt) / 8, 256>>>(fc_out_W, fc_out_b, out);
}

// round 13
// speedup vs baseline: 2.4793x; 1.1000x over previous
#include <cuda_runtime.h>
#include <cuda_fp16.h>
#include <math.h>
#include <stdint.h>

#define Bb 512
#define Ff 64
#define Tt 64
#define Hh 512
#define Kk 4
#define NN (3 * Hh)   // 1536

// ---------------- scratch (static device globals; no allocation) ----------------
__device__ __align__(16) __half g_d[(size_t)Tt * Bb * Ff];        // data fp16 [t][b][f]
__device__ __align__(16) __half g_fcW[(size_t)Kk * Hh * Ff];
__device__ __align__(16) __half g_x[(size_t)Kk * Tt * Bb * Hh];   // x fp16
__device__ __align__(16) __half g_Wih[(size_t)Kk * NN * Hh];
__device__ __align__(16) __half g_Whhc[(size_t)Kk * NN * Hh];     // Whh, composite row order
// ping-pong hidden state (read buf t&1, write buf (t&1)^1)
__device__ __align__(16) __half g_hf[2 * (size_t)Kk * Bb * Hh];
__device__ __align__(16) float g_h[2 * (size_t)Kk * Bb * Hh];
__device__ __align__(16) float g_gi[(size_t)Kk * Tt * Bb * NN];   // [k][(t,b)][3H] plain
__device__ __align__(16) float g_hs[(size_t)Kk * Tt * Bb * Hh];   // [k][t][b][h]

// ---------------- helpers ----------------
__device__ __forceinline__ uint32_t smem_u32(const void* p) {
    uint32_t a;
    asm("{ .reg .u64 t; cvta.to.shared.u64 t, %1; cvt.u32.u64 %0, t; }" : "=r"(a) : "l"(p));
    return a;
}
__device__ __forceinline__ void cp16(uint32_t saddr, const void* g) {
    asm volatile("cp.async.cg.shared.global [%0], [%1], 16;" :: "r"(saddr), "l"(g));
}
__device__ __forceinline__ void cp_commit() {
    asm volatile("cp.async.commit_group;" ::: "memory");
}
template <int N> __device__ __forceinline__ void cp_wait() {
    asm volatile("cp.async.wait_group %0;" :: "n"(N) : "memory");
}
__device__ __forceinline__ void ldsm_x4(uint32_t a, uint32_t* r) {
    asm volatile("ldmatrix.sync.aligned.m8n8.x4.shared.b16 {%0,%1,%2,%3}, [%4];"
                 : "=r"(r[0]), "=r"(r[1]), "=r"(r[2]), "=r"(r[3]) : "r"(a));
}
__device__ __forceinline__ void mma16816(float* d, const uint32_t* a, const uint32_t* b) {
    asm volatile(
        "mma.sync.aligned.m16n8k16.row.col.f32.f16.f16.f32 "
        "{%0,%1,%2,%3}, {%4,%5,%6,%7}, {%8,%9}, {%0,%1,%2,%3};"
        : "+f"(d[0]), "+f"(d[1]), "+f"(d[2]), "+f"(d[3])
        : "r"(a[0]), "r"(a[1]), "r"(a[2]), "r"(a[3]), "r"(b[0]), "r"(b[1]));
}
__device__ __forceinline__ float sigm(float x) { return 1.f / (1.f + expf(-x)); }

// swizzle for 64B rows (k-chunk 32 fp16): chunk (0..3) ^= (row>>1)&3
__device__ __forceinline__ uint32_t swz64(int r, int c) {
    return (uint32_t)(r * 64 + ((c ^ ((r >> 1) & 3)) << 4));
}
// swizzle for 32B rows (k-chunk 16 fp16): chunk (0..1) ^= (row>>2)&1
__device__ __forceinline__ uint32_t swz32(int r, int c) {
    return (uint32_t)(r * 32 + ((c ^ ((r >> 2) & 1)) << 4));
}
// composite col j = 24q + 8g + s  ->  original W row g*512 + 8q + s
__device__ __forceinline__ int c2o(int j) {
    return ((j >> 3) % 3) * Hh + (j / 24) * 8 + (j & 7);
}

// ---------------- data transpose: [B,F,T] -> fp16 [T,B,F] ----------------
__global__ void transpose_data(const float* __restrict__ data) {
    int idx = blockIdx.x * blockDim.x + threadIdx.x;
    if (idx >= Tt * Bb * Ff) return;
    int f = idx % Ff;
    int b = (idx / Ff) % Bb;
    int t = idx / (Ff * Bb);
    g_d[idx] = __float2half(data[(size_t)b * Ff * Tt + (size_t)f * Tt + t]);
}

// ---------------- weight conversion: Wih plain fp16, Whh composite fp16, fcW fp16 ----
__global__ void convert_w(const float* __restrict__ Wih, const float* __restrict__ Whh,
                          const float* __restrict__ fcW) {
    const int NW = Kk * NN * Hh;
    const int NF = Kk * Hh * Ff;
    int idx = blockIdx.x * 256 + threadIdx.x;
    if (idx < NW) {
        g_Wih[idx] = __float2half(Wih[idx]);
    } else if (idx < 2 * NW) {
        // destination-indexed composite permutation of Whh rows
        int i = idx - NW;
        int k = i / (NN * Hh);
        int rem = i - k * (NN * Hh);
        int j = rem / Hh;           // composite row
        int col = rem - j * Hh;
        g_Whhc[i] = __float2half(Whh[((size_t)k * NN + c2o(j)) * Hh + col]);
    } else if (idx < 2 * NW + NF) {
        g_fcW[idx - 2 * NW] = __float2half(fcW[idx - 2 * NW]);
    }
}

// ---------------- h init -> buffer 0 ----------------
__global__ void init_h_kernel(const float* __restrict__ init) {
    int idx = blockIdx.x * 256 + threadIdx.x;   // K*B*H
    float v = init[idx % (Bb * Hh)];
    g_h[idx] = v;
    g_hf[idx] = __float2half(v);
}

// ---------------- proj: fp16 HMMA, M128 x N128, K=64 -> relu -> g_x ----------------
__global__ void __launch_bounds__(256, 2) proj_hmma(const float* __restrict__ fcB) {
    __shared__ __align__(16) char smem[16384];   // 2 stages x (A 4K + B 4K)
    uint32_t sb = smem_u32(smem);
    int tid = threadIdx.x, wid = tid >> 5, lane = tid & 31;
    int z = blockIdx.z;
    int n0 = blockIdx.x * 128, m0 = blockIdx.y * 128;
    int warp_m = wid >> 2, warp_n = wid & 3;      // warp tile 64 x 32
    int t = m0 >> 9, b0 = m0 & 511;
    int tt = (z < 2) ? t : (Tt - 1 - t);

    const __half* A = g_d + ((size_t)tt * Bb + b0) * Ff;
    const __half* Bw = g_fcW + (size_t)z * Hh * Ff;

    float acc[4][4][4];
#pragma unroll
    for (int i = 0; i < 4; i++)
#pragma unroll
        for (int j = 0; j < 4; j++)
#pragma unroll
            for (int q = 0; q < 4; q++) acc[i][j][q] = 0.f;

    auto load_stage = [&](int s, int k0) {
        uint32_t st = sb + s * 8192;
#pragma unroll
        for (int i = 0; i < 2; i++) {
            int idx = tid + i * 256;           // 0..511
            bool isA = idx < 256;
            int li = idx & 255;
            int r = li >> 1, c = li & 1;
            cp16(st + (isA ? 0 : 4096) + swz32(r, c),
                 (isA ? A : Bw) + (size_t)(isA ? r : n0 + r) * Ff + k0 + c * 8);
        }
        cp_commit();
    };

    load_stage(0, 0);
    int cfr = lane >> 4;
    for (int kc = 0; kc < 4; kc++) {
        if (kc + 1 < 4) { load_stage((kc + 1) & 1, (kc + 1) * 16); cp_wait<1>(); }
        else cp_wait<0>();
        __syncthreads();
        uint32_t st = sb + (uint32_t)(kc & 1) * 8192;
        uint32_t a_f[4][4], b_f[4][2];
#pragma unroll
        for (int mi = 0; mi < 4; mi++) {
            int rA = warp_m * 64 + mi * 16 + (lane & 15);
            ldsm_x4(st + swz32(rA, cfr), a_f[mi]);
        }
#pragma unroll
        for (int nj = 0; nj < 2; nj++) {
            int rB = warp_n * 32 + nj * 16 + (lane & 15);
            uint32_t r4[4];
            ldsm_x4(st + 4096 + swz32(rB, cfr), r4);
            b_f[2 * nj][0] = r4[0]; b_f[2 * nj][1] = r4[2];
            b_f[2 * nj + 1][0] = r4[1]; b_f[2 * nj + 1][1] = r4[3];
        }
#pragma unroll
        for (int mi = 0; mi < 4; mi++)
#pragma unroll
            for (int ni = 0; ni < 4; ni++)
                mma16816(acc[mi][ni], a_f[mi], b_f[ni]);
        __syncthreads();
    }

    int lane4 = lane >> 2;
    int cp2 = 2 * (lane & 3);
    const float* bz = fcB + (size_t)z * Hh;
#pragma unroll
    for (int mi = 0; mi < 4; mi++)
#pragma unroll
        for (int v = 0; v < 2; v++) {
            int rl = warp_m * 64 + mi * 16 + lane4 + 8 * v;
            size_t rowoff = (((size_t)z * Tt + t) * Bb + (b0 + rl)) * Hh;
#pragma unroll
            for (int ni = 0; ni < 4; ni++) {
                int h = n0 + warp_n * 32 + ni * 8 + cp2;
                int q = 2 * v;
                __half2 hv;
                hv.x = __float2half(fmaxf(acc[mi][ni][q] + bz[h], 0.f));
                hv.y = __float2half(fmaxf(acc[mi][ni][q + 1] + bz[h + 1], 0.f));
                *(__half2*)(g_x + rowoff + h) = hv;
            }
        }
}

// ---------------- gi GEMM: fp16, CTA 128x128, warp 32x64, k-chunk 32, 3 stages ------
// C[m][n] = sum_i x[m][i]*Wih[n][i] + bih[n]  (plain layout)
__global__ void __launch_bounds__(256, 1) gemm_gi(const float* __restrict__ biasb) {
    __shared__ __align__(16) char smem[49152];   // 3 stages x (A 8K + B 8K)
    uint32_t sb = smem_u32(smem);

    int tid = threadIdx.x, wid = tid >> 5, lane = tid & 31;
    int z = blockIdx.z;
    int n0 = blockIdx.x * 128, m0 = blockIdx.y * 128;
    int warp_m = wid >> 1;     // 4 warps over M (32 rows each)
    int warp_n = wid & 1;      // 2 warps over N (64 cols each)

    const __half* A = g_x + (size_t)z * Tt * Bb * Hh;
    const __half* Bw = g_Wih + (size_t)z * NN * Hh;
    float* C = g_gi + (size_t)z * Tt * Bb * NN;
    const float* bias = biasb + (size_t)z * NN;

    float acc[2][8][4];
#pragma unroll
    for (int i = 0; i < 2; i++)
#pragma unroll
        for (int j = 0; j < 8; j++)
#pragma unroll
            for (int q = 0; q < 4; q++) acc[i][j][q] = 0.f;

    auto load_stage = [&](int s, int k0) {
        uint32_t st = sb + (uint32_t)s * 16384;
#pragma unroll
        for (int i = 0; i < 4; i++) {
            int idx = tid + i * 256;            // 0..1023
            bool isA = idx < 512;
            int li = idx & 511;
            int r = li >> 2, c = li & 3;
            cp16(st + (isA ? 0 : 8192) + swz64(r, c),
                 (isA ? A : Bw) + (size_t)((isA ? m0 : n0) + r) * Hh + k0 + c * 8);
        }
        cp_commit();
    };

    load_stage(0, 0);
    load_stage(1, 32);

    for (int kc = 0; kc < 16; kc++) {
        if (kc + 2 < 16) { load_stage((kc + 2) % 3, (kc + 2) * 32); cp_wait<2>(); }
        else if (kc + 1 < 16) cp_wait<1>();
        else cp_wait<0>();
        __syncthreads();

        uint32_t st = sb + (uint32_t)(kc % 3) * 16384;
#pragma unroll
        for (int ks = 0; ks < 2; ks++) {
            uint32_t a_f[2][4], b_f[8][2];
            int chunk = ks * 2 + (lane >> 4);
#pragma unroll
            for (int mi = 0; mi < 2; mi++) {
                int rr = warp_m * 32 + mi * 16 + (lane & 15);
                ldsm_x4(st + swz64(rr, chunk), a_f[mi]);
            }
#pragma unroll
            for (int nj = 0; nj < 4; nj++) {
                int rr = warp_n * 64 + nj * 16 + (lane & 15);
                uint32_t r4[4];
                ldsm_x4(st + 8192 + swz64(rr, chunk), r4);
                b_f[2 * nj][0] = r4[0]; b_f[2 * nj][1] = r4[2];
                b_f[2 * nj + 1][0] = r4[1]; b_f[2 * nj + 1][1] = r4[3];
            }
#pragma unroll
            for (int mi = 0; mi < 2; mi++)
#pragma unroll
                for (int ni = 0; ni < 8; ni++)
                    mma16816(acc[mi][ni], a_f[mi], b_f[ni]);
        }
        __syncthreads();
    }

#pragma unroll
    for (int mi = 0; mi < 2; mi++) {
        int row = m0 + warp_m * 32 + mi * 16 + (lane >> 2);
#pragma unroll
        for (int ni = 0; ni < 8; ni++) {
            int col = n0 + warp_n * 64 + ni * 8 + 2 * (lane & 3);
            float2 o0, o1;
            o0.x = acc[mi][ni][0] + bias[col];
            o0.y = acc[mi][ni][1] + bias[col + 1];
            o1.x = acc[mi][ni][2] + bias[col];
            o1.y = acc[mi][ni][3] + bias[col + 1];
            *(float2*)(C + (size_t)row * NN + col) = o0;
            *(float2*)(C + (size_t)(row + 8) * NN + col) = o1;
        }
    }
}

// ---------------- fused step: gh GEMM (composite Whh) + GRU gates ------------------
// CTA tile M=128 x N=192 (composite), k-chunk 32, 2 stages; warp 64x48.
// A = g_hf buf t&1, epilogue writes h into buf (t&1)^1 (ping-pong, no intra-launch WAR).
__global__ void __launch_bounds__(256, 1) gemm_step(const float* __restrict__ bhh, int t) {
    __shared__ __align__(16) char smem[40960];   // 2 stages x (A 8K + B 12K)
    uint32_t sb = smem_u32(smem);

    int tid = threadIdx.x, wid = tid >> 5, lane = tid & 31;
    int zz = blockIdx.z;
    int n0 = blockIdx.x * 192, m0 = blockIdx.y * 128;
    int warp_m = wid >> 2, warp_n = wid & 3;      // warp tile 64 x 48
    int rb = t & 1, wb = rb ^ 1;

    const __half* A = g_hf + ((size_t)rb * Kk + zz) * Bb * Hh;
    const __half* Bw = g_Whhc + (size_t)zz * NN * Hh;

    float acc[4][6][4];
#pragma unroll
    for (int i = 0; i < 4; i++)
#pragma unroll
        for (int j = 0; j < 6; j++)
#pragma unroll
            for (int q = 0; q < 4; q++) acc[i][j][q] = 0.f;

    // 1280 16B chunks per stage / 256 threads = 5
    auto load_stage = [&](int s, int k0) {
        uint32_t st = sb + (uint32_t)s * 20480;
#pragma unroll
        for (int i = 0; i < 2; i++) {          // A: 512 chunks
            int idx = tid + i * 256;
            int r = idx >> 2, c = idx & 3;
            cp16(st + swz64(r, c), A + (size_t)(m0 + r) * Hh + k0 + c * 8);
        }
#pragma unroll
        for (int i = 2; i < 5; i++) {          // B: 768 chunks
            int li = tid + (i - 2) * 256;
            int r = li >> 2, c = li & 3;
            cp16(st + 8192 + swz64(r, c), Bw + (size_t)(n0 + r) * Hh + k0 + c * 8);
        }
        cp_commit();
    };

    load_stage(0, 0);

    for (int kc = 0; kc < 16; kc++) {
        if (kc + 1 < 16) { load_stage((kc + 1) & 1, (kc + 1) * 32); cp_wait<1>(); }
        else cp_wait<0>();
        __syncthreads();

        uint32_t st = sb + (uint32_t)(kc & 1) * 20480;
#pragma unroll
        for (int ks = 0; ks < 2; ks++) {
            uint32_t a_f[4][4], b_f[6][2];
            int chunk = ks * 2 + (lane >> 4);
#pragma unroll
            for (int mi = 0; mi < 4; mi++) {
                int rA = warp_m * 64 + mi * 16 + (lane & 15);
                ldsm_x4(st + swz64(rA, chunk), a_f[mi]);
            }
#pragma unroll
            for (int nj = 0; nj < 3; nj++) {
                int rB = warp_n * 48 + nj * 16 + (lane & 15);
                uint32_t r4[4];
                ldsm_x4(st + 8192 + swz64(rB, chunk), r4);
                b_f[2 * nj][0] = r4[0]; b_f[2 * nj][1] = r4[2];
                b_f[2 * nj + 1][0] = r4[1]; b_f[2 * nj + 1][1] = r4[3];
            }
#pragma unroll
            for (int mi = 0; mi < 4; mi++)
#pragma unroll
                for (int ni = 0; ni < 6; ni++)
                    mma16816(acc[mi][ni], a_f[mi], b_f[ni]);
        }
        __syncthreads();
    }

    // ---- fused GRU gates (in registers), plain gi/bias reads ----
    int lane4 = lane >> 2;
    int cp2 = 2 * (lane & 3);
    const float* giK = g_gi + (size_t)zz * Tt * Bb * NN;
    const float* bz = bhh + (size_t)zz * NN;
#pragma unroll
    for (int tr = 0; tr < 2; tr++) {
        int jr = n0 + warp_n * 48 + tr * 24;    // composite col of this triple's r-tile
        int h0e = (jr / 24) * 8 + cp2;          // h index pair handled by this thread
        float br0 = bz[h0e],          br1 = bz[h0e + 1];
        float bz0 = bz[Hh + h0e],     bz1 = bz[Hh + h0e + 1];
        float bn0 = bz[2 * Hh + h0e], bn1 = bz[2 * Hh + h0e + 1];
#pragma unroll
        for (int mi = 0; mi < 4; mi++)
#pragma unroll
            for (int v = 0; v < 2; v++) {
                int b = m0 + warp_m * 64 + mi * 16 + lane4 + 8 * v;
                const float* gi = giK + ((size_t)t * Bb + b) * NN;
                float2 gir = *(const float2*)(gi + h0e);
                float2 giz = *(const float2*)(gi + Hh + h0e);
                float2 gin = *(const float2*)(gi + 2 * Hh + h0e);
                float2 hp = *(const float2*)(
                    g_h + (((size_t)rb * Kk + zz) * Bb + b) * Hh + h0e);
                int q = 2 * v;
                float R0 = sigm(gir.x + acc[mi][3 * tr + 0][q] + br0);
                float Z0 = sigm(giz.x + acc[mi][3 * tr + 1][q] + bz0);
                float N0 = tanhf(gin.x + R0 * (acc[mi][3 * tr + 2][q] + bn0));
                float hn0 = (1.f - Z0) * N0 + Z0 * hp.x;
                float R1 = sigm(gir.y + acc[mi][3 * tr + 0][q + 1] + br1);
                float Z1 = sigm(giz.y + acc[mi][3 * tr + 1][q + 1] + bz1);
                float N1 = tanhf(gin.y + R1 * (acc[mi][3 * tr + 2][q + 1] + bn1));
                float hn1 = (1.f - Z1) * N1 + Z1 * hp.y;

                size_t hoff = (((size_t)wb * Kk + zz) * Bb + b) * Hh + h0e;
                *(float2*)(g_h + hoff) = make_float2(hn0, hn1);
                *(float2*)(g_hs + (((size_t)zz * Tt + t) * Bb + b) * Hh + h0e) =
                    make_float2(hn0, hn1);
                __half2 hv;
                hv.x = __float2half(hn0);
                hv.y = __float2half(hn1);
                *(__half2*)(g_hf + hoff) = hv;
            }
    }
}

// ---------------- output heads ----------------
__global__ void out_kernel(const float* __restrict__ Wout,
                           const float* __restrict__ bout,
                           float* __restrict__ out) {
    int warp = threadIdx.x >> 5;
    int lane = threadIdx.x & 31;
    int oid = blockIdx.x * 8 + warp;
    int pair = oid >> 15;
    int rem = oid & 32767;
    int b = rem >> 6;
    int t = rem & 63;
    const float* hf = g_hs + (((size_t)pair * Tt + t) * Bb + b) * Hh;
    const float* hb = g_hs + (((size_t)(pair + 2) * Tt + (Tt - 1 - t)) * Bb + b) * Hh;
    const float* w = Wout + pair * Hh;
    float s = 0.f;
    for (int i0 = lane * 4; i0 < Hh; i0 += 128) {
        float4 f = *(const float4*)(hf + i0);
        float4 g = *(const float4*)(hb + i0);
        float4 wv = *(const float4*)(w + i0);
        s += (f.x + g.x) * wv.x + (f.y + g.y) * wv.y +
             (f.z + g.z) * wv.z + (f.w + g.w) * wv.w;
    }
#pragma unroll
    for (int o = 16; o; o >>= 1) s += __shfl_xor_sync(0xffffffffu, s, o);
    if (lane == 0) out[(size_t)pair * Bb * Tt + b * Tt + t] = s + bout[pair];
}

// ---------------- launch (kernel launches ONLY) ----------------
extern "C" void kernel_launch(void* const* d_in, const int* in_sizes, int n_in,
                              void* d_out, int out_size) {
    const float* data     = (const float*)d_in[0];
    const float* init     = (const float*)d_in[1];
    const float* fc_in_W  = (const float*)d_in[2];
    const float* fc_in_b  = (const float*)d_in[3];
    const float* Wih      = (const float*)d_in[4];
    const float* Whh      = (const float*)d_in[5];
    const float* bih      = (const float*)d_in[6];
    const float* bhh      = (const float*)d_in[7];
    const float* fc_out_W = (const float*)d_in[8];
    const float* fc_out_b = (const float*)d_in[9];
    float* out = (float*)d_out;

    transpose_data<<<(Tt * Bb * Ff) / 256, 256>>>(data);
    convert_w<<<(2 * Kk * NN * Hh + Kk * Hh * Ff) / 256, 256>>>(Wih, Whh, fc_in_W);

    // proj (fp16 HMMA): M = T*B per cell, N = 512, K = 64
    proj_hmma<<<dim3(Hh / 128, (Tt * Bb) / 128, Kk), 256>>>(fc_in_b);

    // gi = xseq @ Wih^T + bih : M = T*B = 32768
    gemm_gi<<<dim3(NN / 128, (Tt * Bb) / 128, Kk), 256>>>(bih);

    init_h_kernel<<<(Kk * Bb * Hh) / 256, 256>>>(init);

    for (int t = 0; t < Tt; t++) {
        // fused gh GEMM + gates: grid (8, 4, 4) = 128 CTAs, one launch per step
        gemm_step<<<dim3(NN / 192, Bb / 128, Kk), 256>>>(bhh, t);
    }

    out_kernel<<<(2 * Bb * Tt) / 8, 256>>>(fc_out_W, fc_out_b, out);
}